// round 8
// baseline (speedup 1.0000x reference)
#include <cuda_runtime.h>
#include <cuda_bf16.h>
#include <math.h>
#include <cstdint>

// Problem constants
#define BATCH 2
#define SEQ 2048
#define DM 1024
#define NH 16
#define DH 64
#define MROWS (BATCH * SEQ)   // 4096

// ---------------------------------------------------------------------------
// Scratch (no cudaMalloc allowed)
// ---------------------------------------------------------------------------
__device__ float g_Q[MROWS * DM];
__device__ float g_K[MROWS * DM];
__device__ float g_V[MROWS * DM];
__device__ float g_C[MROWS * DM];

// ---------------------------------------------------------------------------
// Common helpers
// ---------------------------------------------------------------------------
__device__ __forceinline__ void mma_tf32(float& c0, float& c1, float& c2, float& c3,
                                         uint32_t a0, uint32_t a1, uint32_t a2, uint32_t a3,
                                         uint32_t b0, uint32_t b1) {
    asm volatile(
        "mma.sync.aligned.m16n8k8.row.col.f32.tf32.tf32.f32 "
        "{%0,%1,%2,%3}, {%4,%5,%6,%7}, {%8,%9}, {%0,%1,%2,%3};"
        : "+f"(c0), "+f"(c1), "+f"(c2), "+f"(c3)
        : "r"(a0), "r"(a1), "r"(a2), "r"(a3), "r"(b0), "r"(b1));
}

// fp32 -> tf32 round-to-nearest bit trick (HW truncates; +0x1000 completes RN)
__device__ __forceinline__ uint32_t rnd_tf32(uint32_t x) { return x + 0x1000u; }
__device__ __forceinline__ uint32_t rnd_tf32f(float x) { return __float_as_uint(x) + 0x1000u; }

__device__ __forceinline__ float ex2f(float x) {
    float y;
    asm("ex2.approx.f32 %0, %1;" : "=f"(y) : "f"(x));
    return y;
}

// ---------------------------------------------------------------------------
// tf32 mma.sync GEMM: C[M,N] = A[M,K] * W[N,K]^T + bias[N]
// Tile 128x128x32, 256 threads. Double-buffered smem, ONE barrier per chunk.
// (unchanged from R7 — measured flat vs R6)
// ---------------------------------------------------------------------------
#define BM 128
#define BN 128
#define BK 32
#define KPAD 36
#define NCHUNK (DM / BK)
#define ABUFU (BM * KPAD)
#define GEMM_SMEM_BYTES (4 * ABUFU * 4)

__global__ __launch_bounds__(256, 2) void gemm_tf32_kernel(
    const float* __restrict__ A, const float* __restrict__ W,
    const float* __restrict__ bias, float* __restrict__ C)
{
    extern __shared__ uint32_t gsm[];
    uint32_t* As0 = gsm;
    uint32_t* Bs0 = gsm + 2 * ABUFU;

    const int tid = threadIdx.x;
    const int wid = tid >> 5;
    const int lane = tid & 31;
    const int gid = lane >> 2;
    const int tig = lane & 3;

    const int wm = wid >> 2;
    const int wn = wid & 3;

    const int m0 = blockIdx.y * BM;
    const int n0 = blockIdx.x * BN;

    const int grow = tid >> 3;
    const int gcol = (tid & 7) * 4;

    const uint4* Ag = (const uint4*)(A + (long)(m0 + grow) * DM + gcol);
    const uint4* Wg = (const uint4*)(W + (long)(n0 + grow) * DM + gcol);

    float acc[4][4][4];
    #pragma unroll
    for (int i = 0; i < 4; i++)
        #pragma unroll
        for (int j = 0; j < 4; j++)
            #pragma unroll
            for (int c = 0; c < 4; c++) acc[i][j][c] = 0.0f;

    uint4 ra[4], rb[4];
    #pragma unroll
    for (int i = 0; i < 4; i++) {
        ra[i] = Ag[(long)i * 32 * (DM / 4)];
        rb[i] = Wg[(long)i * 32 * (DM / 4)];
    }
    #pragma unroll
    for (int i = 0; i < 4; i++) {
        uint4 va = make_uint4(rnd_tf32(ra[i].x), rnd_tf32(ra[i].y),
                              rnd_tf32(ra[i].z), rnd_tf32(ra[i].w));
        *(uint4*)&As0[(grow + i * 32) * KPAD + gcol] = va;
        uint4 vb = make_uint4(rnd_tf32(rb[i].x), rnd_tf32(rb[i].y),
                              rnd_tf32(rb[i].z), rnd_tf32(rb[i].w));
        *(uint4*)&Bs0[(grow + i * 32) * KPAD + gcol] = vb;
    }
    __syncthreads();

    for (int c = 0; c < NCHUNK; c++) {
        const uint32_t* As = As0 + (c & 1) * ABUFU;
        const uint32_t* Bs = Bs0 + (c & 1) * ABUFU;

        if (c + 1 < NCHUNK) {
            const uint4* an = Ag + (long)(c + 1) * (BK / 4);
            const uint4* bn = Wg + (long)(c + 1) * (BK / 4);
            #pragma unroll
            for (int i = 0; i < 4; i++) {
                ra[i] = an[(long)i * 32 * (DM / 4)];
                rb[i] = bn[(long)i * 32 * (DM / 4)];
            }
        }

        #pragma unroll
        for (int ks = 0; ks < 4; ks++) {
            const int k0 = ks * 8;
            uint32_t af[4][4], bf[4][2];
            #pragma unroll
            for (int mt = 0; mt < 4; mt++) {
                const int r = wm * 64 + mt * 16 + gid;
                af[mt][0] = As[r * KPAD + k0 + tig];
                af[mt][1] = As[(r + 8) * KPAD + k0 + tig];
                af[mt][2] = As[r * KPAD + k0 + tig + 4];
                af[mt][3] = As[(r + 8) * KPAD + k0 + tig + 4];
            }
            #pragma unroll
            for (int nt = 0; nt < 4; nt++) {
                const int r = wn * 32 + nt * 8 + gid;
                bf[nt][0] = Bs[r * KPAD + k0 + tig];
                bf[nt][1] = Bs[r * KPAD + k0 + tig + 4];
            }
            #pragma unroll
            for (int mt = 0; mt < 4; mt++)
                #pragma unroll
                for (int nt = 0; nt < 4; nt++)
                    mma_tf32(acc[mt][nt][0], acc[mt][nt][1],
                             acc[mt][nt][2], acc[mt][nt][3],
                             af[mt][0], af[mt][1], af[mt][2], af[mt][3],
                             bf[nt][0], bf[nt][1]);
        }

        if (c + 1 < NCHUNK) {
            uint32_t* An = As0 + ((c + 1) & 1) * ABUFU;
            uint32_t* Bn = Bs0 + ((c + 1) & 1) * ABUFU;
            #pragma unroll
            for (int i = 0; i < 4; i++) {
                uint4 va = make_uint4(rnd_tf32(ra[i].x), rnd_tf32(ra[i].y),
                                      rnd_tf32(ra[i].z), rnd_tf32(ra[i].w));
                *(uint4*)&An[(grow + i * 32) * KPAD + gcol] = va;
                uint4 vb = make_uint4(rnd_tf32(rb[i].x), rnd_tf32(rb[i].y),
                                      rnd_tf32(rb[i].z), rnd_tf32(rb[i].w));
                *(uint4*)&Bn[(grow + i * 32) * KPAD + gcol] = vb;
            }
        }
        __syncthreads();
    }

    #pragma unroll
    for (int mt = 0; mt < 4; mt++) {
        const int mrow = m0 + wm * 64 + mt * 16 + gid;
        #pragma unroll
        for (int nt = 0; nt < 4; nt++) {
            const int ncol = n0 + wn * 32 + nt * 8 + tig * 2;
            const float bx = bias[ncol];
            const float by = bias[ncol + 1];
            float2 v0 = make_float2(acc[mt][nt][0] + bx, acc[mt][nt][1] + by);
            float2 v1 = make_float2(acc[mt][nt][2] + bx, acc[mt][nt][3] + by);
            *(float2*)(C + (long)mrow * DM + ncol) = v0;
            *(float2*)(C + (long)(mrow + 8) * DM + ncol) = v1;
        }
    }
}

// ---------------------------------------------------------------------------
// Tensor-core flash attention, 128 threads (4 warps), 32 q-rows per warp.
// Each B-fragment LDS feeds TWO m16 MMAs -> K/V crossbar traffic per q-row
// halves vs the 8-warp x 16-row layout. Single-buffer K/V (no reg staging
// — R7 spill lesson). 2 CTAs/SM.
// Smem: Ps[128][68] (Q staging + P roundtrip), Ks[64][68], Vt[64][68].
// ---------------------------------------------------------------------------
#define APAD 68
#define ATT_SMEM_U32 (128 * APAD + 2 * (64 * APAD))
#define ATT_SMEM_BYTES (ATT_SMEM_U32 * 4)

__global__ __launch_bounds__(128, 2) void attn_mma_kernel(
    const float* __restrict__ Q, const float* __restrict__ K,
    const float* __restrict__ V, float* __restrict__ Ctx)
{
    extern __shared__ uint32_t sm[];
    uint32_t* Ps = sm;                    // [128][APAD]
    uint32_t* Ks = sm + 128 * APAD;       // [64][APAD]
    uint32_t* Vt = Ks + 64 * APAD;        // [64][APAD]

    const int bh = blockIdx.y;
    const int b  = bh >> 4;
    const int h  = bh & 15;
    const int q0 = blockIdx.x * 128;

    const int tid  = threadIdx.x;
    const int wid  = tid >> 5;
    const int lane = tid & 31;
    const int gid  = lane >> 2;
    const int tig  = lane & 3;
    const int rw   = wid * 32;            // warp's q-row base (32 rows)

    const float* Qg = Q + ((long)b * SEQ) * DM + h * DH;
    const float* Kg = K + ((long)b * SEQ) * DM + h * DH;
    const float* Vg = V + ((long)b * SEQ) * DM + h * DH;

    // K/V staging coords: 2 threads per key row, 32 dh each
    const int tkey = tid & 63;
    const int dhb  = (tid >> 6) * 32;

    const float cf = 0.125f * 1.44269504088896f;   // 1/sqrt(64) * log2(e)

    // ---- stage Q (scaled into log2 domain): one row per thread
    {
        const float4* qp = (const float4*)(Qg + (long)(q0 + tid) * DM);
        #pragma unroll
        for (int j = 0; j < 16; j++) {
            float4 v = qp[j];
            uint32_t* d = &Ps[tid * APAD + j * 4];
            d[0] = rnd_tf32f(v.x * cf);
            d[1] = rnd_tf32f(v.y * cf);
            d[2] = rnd_tf32f(v.z * cf);
            d[3] = rnd_tf32f(v.w * cf);
        }
    }
    __syncthreads();

    // ---- persistent Q fragments: 2 m16 tiles per warp
    uint32_t qf[2][8][4];
    #pragma unroll
    for (int m = 0; m < 2; m++) {
        const int r = rw + m * 16 + gid;
        #pragma unroll
        for (int ks = 0; ks < 8; ks++) {
            qf[m][ks][0] = Ps[r * APAD + ks * 8 + tig];
            qf[m][ks][1] = Ps[(r + 8) * APAD + ks * 8 + tig];
            qf[m][ks][2] = Ps[r * APAD + ks * 8 + tig + 4];
            qf[m][ks][3] = Ps[(r + 8) * APAD + ks * 8 + tig + 4];
        }
    }

    float o[2][8][4];
    #pragma unroll
    for (int m = 0; m < 2; m++)
        #pragma unroll
        for (int nt = 0; nt < 8; nt++)
            #pragma unroll
            for (int c = 0; c < 4; c++) o[m][nt][c] = 0.0f;
    float mr[2][2], l[2][2];
    #pragma unroll
    for (int m = 0; m < 2; m++) {
        mr[m][0] = -INFINITY; mr[m][1] = -INFINITY;
        l[m][0] = 0.0f; l[m][1] = 0.0f;
    }

    const int NT = SEQ / 64;
    for (int it = 0; it < NT; it++) {
        __syncthreads();   // prior-tile fragment reads complete

        // ---- stage K tile [key][dh] and V^T tile [dh][key]
        {
            const long kr = (long)(it * 64 + tkey);
            const float4* kp = (const float4*)(Kg + kr * DM + dhb);
            const float4* vp = (const float4*)(Vg + kr * DM + dhb);
            #pragma unroll
            for (int j = 0; j < 8; j++) {
                float4 kv = kp[j];
                uint4 w = make_uint4(rnd_tf32f(kv.x), rnd_tf32f(kv.y),
                                     rnd_tf32f(kv.z), rnd_tf32f(kv.w));
                *(uint4*)&Ks[tkey * APAD + dhb + 4 * j] = w;
                float4 vv = vp[j];
                const int dv = dhb + 4 * j;
                Vt[(dv + 0) * APAD + tkey] = rnd_tf32f(vv.x);
                Vt[(dv + 1) * APAD + tkey] = rnd_tf32f(vv.y);
                Vt[(dv + 2) * APAD + tkey] = rnd_tf32f(vv.z);
                Vt[(dv + 3) * APAD + tkey] = rnd_tf32f(vv.w);
            }
        }
        __syncthreads();

        // ---- S = Q * K^T  (per warp: 32 x 64; B-frags shared by both m-tiles)
        float s[2][8][4];
        #pragma unroll
        for (int m = 0; m < 2; m++)
            #pragma unroll
            for (int nt = 0; nt < 8; nt++)
                #pragma unroll
                for (int c = 0; c < 4; c++) s[m][nt][c] = 0.0f;

        #pragma unroll
        for (int nt = 0; nt < 8; nt++) {
            const uint32_t* kb = &Ks[(nt * 8 + gid) * APAD];
            #pragma unroll
            for (int ks = 0; ks < 8; ks++) {
                uint32_t b0 = kb[ks * 8 + tig];
                uint32_t b1 = kb[ks * 8 + tig + 4];
                mma_tf32(s[0][nt][0], s[0][nt][1], s[0][nt][2], s[0][nt][3],
                         qf[0][ks][0], qf[0][ks][1], qf[0][ks][2], qf[0][ks][3], b0, b1);
                mma_tf32(s[1][nt][0], s[1][nt][1], s[1][nt][2], s[1][nt][3],
                         qf[1][ks][0], qf[1][ks][1], qf[1][ks][2], qf[1][ks][3], b0, b1);
            }
        }

        // ---- online softmax (log2 domain), per m-tile
        #pragma unroll
        for (int m = 0; m < 2; m++) {
            float mt0 = -INFINITY, mt1 = -INFINITY;
            #pragma unroll
            for (int nt = 0; nt < 8; nt++) {
                mt0 = fmaxf(mt0, fmaxf(s[m][nt][0], s[m][nt][1]));
                mt1 = fmaxf(mt1, fmaxf(s[m][nt][2], s[m][nt][3]));
            }
            mt0 = fmaxf(mt0, __shfl_xor_sync(0xffffffffu, mt0, 1));
            mt0 = fmaxf(mt0, __shfl_xor_sync(0xffffffffu, mt0, 2));
            mt1 = fmaxf(mt1, __shfl_xor_sync(0xffffffffu, mt1, 1));
            mt1 = fmaxf(mt1, __shfl_xor_sync(0xffffffffu, mt1, 2));

            const float mn0 = fmaxf(mr[m][0], mt0);
            const float mn1 = fmaxf(mr[m][1], mt1);
            const float a0 = ex2f(mr[m][0] - mn0);
            const float a1 = ex2f(mr[m][1] - mn1);
            mr[m][0] = mn0; mr[m][1] = mn1;

            const int r = rw + m * 16 + gid;
            float rs0 = 0.0f, rs1 = 0.0f;
            #pragma unroll
            for (int nt = 0; nt < 8; nt++) {
                float p0 = ex2f(s[m][nt][0] - mn0);
                float p1 = ex2f(s[m][nt][1] - mn0);
                float p2 = ex2f(s[m][nt][2] - mn1);
                float p3 = ex2f(s[m][nt][3] - mn1);
                rs0 += p0 + p1;
                rs1 += p2 + p3;
                uint2 w0 = make_uint2(rnd_tf32f(p0), rnd_tf32f(p1));
                uint2 w1 = make_uint2(rnd_tf32f(p2), rnd_tf32f(p3));
                *(uint2*)&Ps[r * APAD + nt * 8 + tig * 2] = w0;
                *(uint2*)&Ps[(r + 8) * APAD + nt * 8 + tig * 2] = w1;
            }
            rs0 += __shfl_xor_sync(0xffffffffu, rs0, 1);
            rs0 += __shfl_xor_sync(0xffffffffu, rs0, 2);
            rs1 += __shfl_xor_sync(0xffffffffu, rs1, 1);
            rs1 += __shfl_xor_sync(0xffffffffu, rs1, 2);

            l[m][0] = l[m][0] * a0 + rs0;
            l[m][1] = l[m][1] * a1 + rs1;
            #pragma unroll
            for (int nt = 0; nt < 8; nt++) {
                o[m][nt][0] *= a0; o[m][nt][1] *= a0;
                o[m][nt][2] *= a1; o[m][nt][3] *= a1;
            }
        }
        __syncwarp();   // P stores visible within warp (rows are warp-private)

        // ---- O += P * V  (B-frags shared by both m-tiles)
        #pragma unroll
        for (int ks = 0; ks < 8; ks++) {
            uint32_t pa[2][4];
            #pragma unroll
            for (int m = 0; m < 2; m++) {
                const int r = rw + m * 16 + gid;
                pa[m][0] = Ps[r * APAD + ks * 8 + tig];
                pa[m][1] = Ps[(r + 8) * APAD + ks * 8 + tig];
                pa[m][2] = Ps[r * APAD + ks * 8 + tig + 4];
                pa[m][3] = Ps[(r + 8) * APAD + ks * 8 + tig + 4];
            }
            #pragma unroll
            for (int nt = 0; nt < 8; nt++) {
                const uint32_t* vb = &Vt[(nt * 8 + gid) * APAD];
                uint32_t b0 = vb[ks * 8 + tig];
                uint32_t b1 = vb[ks * 8 + tig + 4];
                mma_tf32(o[0][nt][0], o[0][nt][1], o[0][nt][2], o[0][nt][3],
                         pa[0][0], pa[0][1], pa[0][2], pa[0][3], b0, b1);
                mma_tf32(o[1][nt][0], o[1][nt][1], o[1][nt][2], o[1][nt][3],
                         pa[1][0], pa[1][1], pa[1][2], pa[1][3], b0, b1);
            }
        }
    }

    // ---- epilogue: normalize and write context
    #pragma unroll
    for (int m = 0; m < 2; m++) {
        const float inv0 = 1.0f / l[m][0];
        const float inv1 = 1.0f / l[m][1];
        const int r = rw + m * 16 + gid;
        float* C0 = Ctx + ((long)b * SEQ + q0 + r) * DM + h * DH;
        float* C1 = Ctx + ((long)b * SEQ + q0 + r + 8) * DM + h * DH;
        #pragma unroll
        for (int nt = 0; nt < 8; nt++) {
            const int col = nt * 8 + tig * 2;
            *(float2*)(C0 + col) = make_float2(o[m][nt][0] * inv0, o[m][nt][1] * inv0);
            *(float2*)(C1 + col) = make_float2(o[m][nt][2] * inv1, o[m][nt][3] * inv1);
        }
    }
}

// ---------------------------------------------------------------------------
// kernel_launch  — inputs: q,k,v, Wq,bq, Wk,bk, Wv,bv, Wo,bo
// ---------------------------------------------------------------------------
extern "C" void kernel_launch(void* const* d_in, const int* in_sizes, int n_in,
                              void* d_out, int out_size)
{
    const float* q  = (const float*)d_in[0];
    const float* k  = (const float*)d_in[1];
    const float* v  = (const float*)d_in[2];
    const float* Wq = (const float*)d_in[3];
    const float* bq = (const float*)d_in[4];
    const float* Wk = (const float*)d_in[5];
    const float* bk = (const float*)d_in[6];
    const float* Wv = (const float*)d_in[7];
    const float* bv = (const float*)d_in[8];
    const float* Wo = (const float*)d_in[9];
    const float* bo = (const float*)d_in[10];
    float* out = (float*)d_out;

    float *pQ, *pK, *pV, *pC;
    cudaGetSymbolAddress((void**)&pQ, g_Q);
    cudaGetSymbolAddress((void**)&pK, g_K);
    cudaGetSymbolAddress((void**)&pV, g_V);
    cudaGetSymbolAddress((void**)&pC, g_C);

    cudaFuncSetAttribute(gemm_tf32_kernel,
                         cudaFuncAttributeMaxDynamicSharedMemorySize,
                         GEMM_SMEM_BYTES);
    cudaFuncSetAttribute(attn_mma_kernel,
                         cudaFuncAttributeMaxDynamicSharedMemorySize,
                         ATT_SMEM_BYTES);

    dim3 ggrid(DM / BN, MROWS / BM);     // (8, 32)
    gemm_tf32_kernel<<<ggrid, 256, GEMM_SMEM_BYTES>>>(q, Wq, bq, pQ);
    gemm_tf32_kernel<<<ggrid, 256, GEMM_SMEM_BYTES>>>(k, Wk, bk, pK);
    gemm_tf32_kernel<<<ggrid, 256, GEMM_SMEM_BYTES>>>(v, Wv, bv, pV);

    dim3 agrid(SEQ / 128, BATCH * NH);   // (16, 32)
    attn_mma_kernel<<<agrid, 128, ATT_SMEM_BYTES>>>(pQ, pK, pV, pC);

    gemm_tf32_kernel<<<ggrid, 256, GEMM_SMEM_BYTES>>>(pC, Wo, bo, out);
}

// round 10
// speedup vs baseline: 1.2851x; 1.2851x over previous
#include <cuda_runtime.h>
#include <cuda_bf16.h>
#include <math.h>
#include <cstdint>

// Problem constants
#define BATCH 2
#define SEQ 2048
#define DM 1024
#define NH 16
#define DH 64
#define MROWS (BATCH * SEQ)   // 4096

// ---------------------------------------------------------------------------
// Scratch (no cudaMalloc allowed)
// ---------------------------------------------------------------------------
__device__ __align__(256) float g_Q[MROWS * DM];
__device__ __align__(256) float g_K[MROWS * DM];
__device__ __align__(256) float g_V[MROWS * DM];
__device__ __align__(256) float g_C[MROWS * DM];

// ---------------------------------------------------------------------------
// Common helpers
// ---------------------------------------------------------------------------
__device__ __forceinline__ void mma_tf32(float& c0, float& c1, float& c2, float& c3,
                                         uint32_t a0, uint32_t a1, uint32_t a2, uint32_t a3,
                                         uint32_t b0, uint32_t b1) {
    asm volatile(
        "mma.sync.aligned.m16n8k8.row.col.f32.tf32.tf32.f32 "
        "{%0,%1,%2,%3}, {%4,%5,%6,%7}, {%8,%9}, {%0,%1,%2,%3};"
        : "+f"(c0), "+f"(c1), "+f"(c2), "+f"(c3)
        : "r"(a0), "r"(a1), "r"(a2), "r"(a3), "r"(b0), "r"(b1));
}

// fp32 -> tf32 round-to-nearest bit trick (HW truncates; +0x1000 completes RN)
__device__ __forceinline__ uint32_t rnd_tf32(uint32_t x) { return x + 0x1000u; }
__device__ __forceinline__ uint32_t rnd_tf32f(float x) { return __float_as_uint(x) + 0x1000u; }

__device__ __forceinline__ float ex2f(float x) {
    float y;
    asm("ex2.approx.f32 %0, %1;" : "=f"(y) : "f"(x));
    return y;
}

__device__ __forceinline__ uint32_t smem_u32(const void* p) {
    uint32_t a;
    asm("{ .reg .u64 t; cvta.to.shared.u64 t, %1; cvt.u32.u64 %0, t; }"
        : "=r"(a) : "l"(p));
    return a;
}

#define CP_ASYNC16(dst_u32, src_ptr) \
    asm volatile("cp.async.ca.shared.global [%0], [%1], 16;" \
                 :: "r"(dst_u32), "l"(src_ptr) : "memory")
#define CP_COMMIT()  asm volatile("cp.async.commit_group;" ::: "memory")
#define CP_WAIT0()   asm volatile("cp.async.wait_group 0;" ::: "memory")

// ---------------------------------------------------------------------------
// tf32 mma.sync GEMM: C[M,N] = A[M,K] * W[N,K]^T + bias[N]
// Tile 128x128x32, 256 threads, double-buffered smem, one barrier per chunk.
// (unchanged — measured flat across R6-R8)
// ---------------------------------------------------------------------------
#define BM 128
#define BN 128
#define BK 32
#define KPAD 36
#define NCHUNK (DM / BK)
#define ABUFU (BM * KPAD)
#define GEMM_SMEM_BYTES (4 * ABUFU * 4)

__global__ __launch_bounds__(256, 2) void gemm_tf32_kernel(
    const float* __restrict__ A, const float* __restrict__ W,
    const float* __restrict__ bias, float* __restrict__ C)
{
    extern __shared__ uint32_t gsm[];
    uint32_t* As0 = gsm;
    uint32_t* Bs0 = gsm + 2 * ABUFU;

    const int tid = threadIdx.x;
    const int wid = tid >> 5;
    const int lane = tid & 31;
    const int gid = lane >> 2;
    const int tig = lane & 3;

    const int wm = wid >> 2;
    const int wn = wid & 3;

    const int m0 = blockIdx.y * BM;
    const int n0 = blockIdx.x * BN;

    const int grow = tid >> 3;
    const int gcol = (tid & 7) * 4;

    const uint4* Ag = (const uint4*)(A + (long)(m0 + grow) * DM + gcol);
    const uint4* Wg = (const uint4*)(W + (long)(n0 + grow) * DM + gcol);

    float acc[4][4][4];
    #pragma unroll
    for (int i = 0; i < 4; i++)
        #pragma unroll
        for (int j = 0; j < 4; j++)
            #pragma unroll
            for (int c = 0; c < 4; c++) acc[i][j][c] = 0.0f;

    uint4 ra[4], rb[4];
    #pragma unroll
    for (int i = 0; i < 4; i++) {
        ra[i] = Ag[(long)i * 32 * (DM / 4)];
        rb[i] = Wg[(long)i * 32 * (DM / 4)];
    }
    #pragma unroll
    for (int i = 0; i < 4; i++) {
        uint4 va = make_uint4(rnd_tf32(ra[i].x), rnd_tf32(ra[i].y),
                              rnd_tf32(ra[i].z), rnd_tf32(ra[i].w));
        *(uint4*)&As0[(grow + i * 32) * KPAD + gcol] = va;
        uint4 vb = make_uint4(rnd_tf32(rb[i].x), rnd_tf32(rb[i].y),
                              rnd_tf32(rb[i].z), rnd_tf32(rb[i].w));
        *(uint4*)&Bs0[(grow + i * 32) * KPAD + gcol] = vb;
    }
    __syncthreads();

    for (int c = 0; c < NCHUNK; c++) {
        const uint32_t* As = As0 + (c & 1) * ABUFU;
        const uint32_t* Bs = Bs0 + (c & 1) * ABUFU;

        if (c + 1 < NCHUNK) {
            const uint4* an = Ag + (long)(c + 1) * (BK / 4);
            const uint4* bn = Wg + (long)(c + 1) * (BK / 4);
            #pragma unroll
            for (int i = 0; i < 4; i++) {
                ra[i] = an[(long)i * 32 * (DM / 4)];
                rb[i] = bn[(long)i * 32 * (DM / 4)];
            }
        }

        #pragma unroll
        for (int ks = 0; ks < 4; ks++) {
            const int k0 = ks * 8;
            uint32_t af[4][4], bf[4][2];
            #pragma unroll
            for (int mt = 0; mt < 4; mt++) {
                const int r = wm * 64 + mt * 16 + gid;
                af[mt][0] = As[r * KPAD + k0 + tig];
                af[mt][1] = As[(r + 8) * KPAD + k0 + tig];
                af[mt][2] = As[r * KPAD + k0 + tig + 4];
                af[mt][3] = As[(r + 8) * KPAD + k0 + tig + 4];
            }
            #pragma unroll
            for (int nt = 0; nt < 4; nt++) {
                const int r = wn * 32 + nt * 8 + gid;
                bf[nt][0] = Bs[r * KPAD + k0 + tig];
                bf[nt][1] = Bs[r * KPAD + k0 + tig + 4];
            }
            #pragma unroll
            for (int mt = 0; mt < 4; mt++)
                #pragma unroll
                for (int nt = 0; nt < 4; nt++)
                    mma_tf32(acc[mt][nt][0], acc[mt][nt][1],
                             acc[mt][nt][2], acc[mt][nt][3],
                             af[mt][0], af[mt][1], af[mt][2], af[mt][3],
                             bf[nt][0], bf[nt][1]);
        }

        if (c + 1 < NCHUNK) {
            uint32_t* An = As0 + ((c + 1) & 1) * ABUFU;
            uint32_t* Bn = Bs0 + ((c + 1) & 1) * ABUFU;
            #pragma unroll
            for (int i = 0; i < 4; i++) {
                uint4 va = make_uint4(rnd_tf32(ra[i].x), rnd_tf32(ra[i].y),
                                      rnd_tf32(ra[i].z), rnd_tf32(ra[i].w));
                *(uint4*)&An[(grow + i * 32) * KPAD + gcol] = va;
                uint4 vb = make_uint4(rnd_tf32(rb[i].x), rnd_tf32(rb[i].y),
                                      rnd_tf32(rb[i].z), rnd_tf32(rb[i].w));
                *(uint4*)&Bn[(grow + i * 32) * KPAD + gcol] = vb;
            }
        }
        __syncthreads();
    }

    #pragma unroll
    for (int mt = 0; mt < 4; mt++) {
        const int mrow = m0 + wm * 64 + mt * 16 + gid;
        #pragma unroll
        for (int nt = 0; nt < 4; nt++) {
            const int ncol = n0 + wn * 32 + nt * 8 + tig * 2;
            const float bx = bias[ncol];
            const float by = bias[ncol + 1];
            float2 v0 = make_float2(acc[mt][nt][0] + bx, acc[mt][nt][1] + by);
            float2 v1 = make_float2(acc[mt][nt][2] + bx, acc[mt][nt][3] + by);
            *(float2*)(C + (long)mrow * DM + ncol) = v0;
            *(float2*)(C + (long)(mrow + 8) * DM + ncol) = v1;
        }
    }
}

// ---------------------------------------------------------------------------
// Tensor-core flash attention — R6 structure (8 warps x 16 q-rows, 256 thr)
// + cp.async double-buffered K/V (register-free prefetch).
// K and V both stored [key][dh] with row stride 72:
//   QK B-frag:  Ks[(nt*8+gid)*72 + ks*8+tig(+4)]  -> bank 8*gid+tig  (CF)
//   PV B-frag:  Vs[(ks*8+tig)*72 + nt*8+gid]       -> bank 8*tig+gid  (CF)
// tf32 RN rounding applied to B-fragments after LDS (cp.async copies raw).
// Smem: Ps[128][68] + 2 x {Ks[64][72], Vs[64][72]} = 108544 B, 2 CTAs/SM.
// ---------------------------------------------------------------------------
#define APAD 68
#define KVPAD 72
#define TILEU (64 * KVPAD)
#define ATT_SMEM_U32 (128 * APAD + 4 * TILEU)
#define ATT_SMEM_BYTES (ATT_SMEM_U32 * 4)

__global__ __launch_bounds__(256, 2) void attn_mma_kernel(
    const float* __restrict__ Q, const float* __restrict__ K,
    const float* __restrict__ V, float* __restrict__ Ctx)
{
    extern __shared__ uint32_t sm[];
    uint32_t* Ps  = sm;                   // [128][APAD]
    uint32_t* KV0 = sm + 128 * APAD;      // 2 x (Ks[64][72], Vs[64][72])

    const int bh = blockIdx.y;
    const int b  = bh >> 4;
    const int h  = bh & 15;
    const int q0 = blockIdx.x * 128;

    const int tid  = threadIdx.x;
    const int wid  = tid >> 5;
    const int lane = tid & 31;
    const int gid  = lane >> 2;
    const int tig  = lane & 3;
    const int r0   = wid * 16 + gid;

    const float* Qg = Q + ((long)b * SEQ) * DM + h * DH;
    const float* Kg = K + ((long)b * SEQ) * DM + h * DH;
    const float* Vg = V + ((long)b * SEQ) * DM + h * DH;

    // cp.async staging coords: 4 threads per key row, 16 dh floats each
    const int tkey = tid & 63;
    const int dhb  = (tid >> 6) * 16;
    const uint32_t kv_base = smem_u32(KV0);

    const float cf = 0.125f * 1.44269504088896f;   // 1/sqrt(64) * log2(e)

    // ---- issue tile 0 K/V copies
    {
        const float* kp = Kg + (long)tkey * DM + dhb;
        const float* vp = Vg + (long)tkey * DM + dhb;
        const uint32_t kd = kv_base + (tkey * KVPAD + dhb) * 4;
        const uint32_t vd = kd + TILEU * 4;
        #pragma unroll
        for (int j = 0; j < 4; j++) {
            CP_ASYNC16(kd + j * 16, kp + j * 4);
            CP_ASYNC16(vd + j * 16, vp + j * 4);
        }
        CP_COMMIT();
    }

    // ---- stage Q (scaled into log2 domain) into Ps
    {
        const int row  = tid >> 1;
        const int col0 = (tid & 1) * 32;
        const float4* qp = (const float4*)(Qg + (long)(q0 + row) * DM + col0);
        #pragma unroll
        for (int j = 0; j < 8; j++) {
            float4 v = qp[j];
            uint32_t* d = &Ps[row * APAD + col0 + j * 4];
            d[0] = rnd_tf32f(v.x * cf);
            d[1] = rnd_tf32f(v.y * cf);
            d[2] = rnd_tf32f(v.z * cf);
            d[3] = rnd_tf32f(v.w * cf);
        }
    }
    __syncthreads();

    // ---- persistent Q fragments
    uint32_t qf[8][4];
    #pragma unroll
    for (int ks = 0; ks < 8; ks++) {
        qf[ks][0] = Ps[r0 * APAD + ks * 8 + tig];
        qf[ks][1] = Ps[(r0 + 8) * APAD + ks * 8 + tig];
        qf[ks][2] = Ps[r0 * APAD + ks * 8 + tig + 4];
        qf[ks][3] = Ps[(r0 + 8) * APAD + ks * 8 + tig + 4];
    }

    float o[8][4];
    #pragma unroll
    for (int nt = 0; nt < 8; nt++)
        #pragma unroll
        for (int c = 0; c < 4; c++) o[nt][c] = 0.0f;
    float mr0 = -INFINITY, mr1 = -INFINITY, l0 = 0.0f, l1 = 0.0f;

    const int NT = SEQ / 64;
    for (int it = 0; it < NT; it++) {
        CP_WAIT0();
        __syncthreads();   // tile it visible; all warps done with prior tile

        // issue next tile's copies into the other buffer (overlaps compute)
        if (it + 1 < NT) {
            const long kr = (long)((it + 1) * 64 + tkey);
            const float* kp = Kg + kr * DM + dhb;
            const float* vp = Vg + kr * DM + dhb;
            const uint32_t kd = kv_base + (((it + 1) & 1) * 2 * TILEU
                                           + tkey * KVPAD + dhb) * 4;
            const uint32_t vd = kd + TILEU * 4;
            #pragma unroll
            for (int j = 0; j < 4; j++) {
                CP_ASYNC16(kd + j * 16, kp + j * 4);
                CP_ASYNC16(vd + j * 16, vp + j * 4);
            }
            CP_COMMIT();
        }

        const uint32_t* Ks = KV0 + (it & 1) * (2 * TILEU);
        const uint32_t* Vs = Ks + TILEU;

        // ---- S = Q * K^T  (per warp: 16 x 64)
        float s[8][4];
        #pragma unroll
        for (int nt = 0; nt < 8; nt++)
            #pragma unroll
            for (int c = 0; c < 4; c++) s[nt][c] = 0.0f;

        #pragma unroll
        for (int nt = 0; nt < 8; nt++) {
            const uint32_t* kb = &Ks[(nt * 8 + gid) * KVPAD];
            #pragma unroll
            for (int ks = 0; ks < 8; ks++) {
                uint32_t b0 = rnd_tf32(kb[ks * 8 + tig]);
                uint32_t b1 = rnd_tf32(kb[ks * 8 + tig + 4]);
                mma_tf32(s[nt][0], s[nt][1], s[nt][2], s[nt][3],
                         qf[ks][0], qf[ks][1], qf[ks][2], qf[ks][3], b0, b1);
            }
        }

        // ---- online softmax (log2 domain)
        float mt0 = -INFINITY, mt1 = -INFINITY;
        #pragma unroll
        for (int nt = 0; nt < 8; nt++) {
            mt0 = fmaxf(mt0, fmaxf(s[nt][0], s[nt][1]));
            mt1 = fmaxf(mt1, fmaxf(s[nt][2], s[nt][3]));
        }
        mt0 = fmaxf(mt0, __shfl_xor_sync(0xffffffffu, mt0, 1));
        mt0 = fmaxf(mt0, __shfl_xor_sync(0xffffffffu, mt0, 2));
        mt1 = fmaxf(mt1, __shfl_xor_sync(0xffffffffu, mt1, 1));
        mt1 = fmaxf(mt1, __shfl_xor_sync(0xffffffffu, mt1, 2));

        const float mn0 = fmaxf(mr0, mt0);
        const float mn1 = fmaxf(mr1, mt1);
        const float a0 = ex2f(mr0 - mn0);
        const float a1 = ex2f(mr1 - mn1);
        mr0 = mn0; mr1 = mn1;

        float rs0 = 0.0f, rs1 = 0.0f;
        #pragma unroll
        for (int nt = 0; nt < 8; nt++) {
            float p0 = ex2f(s[nt][0] - mn0);
            float p1 = ex2f(s[nt][1] - mn0);
            float p2 = ex2f(s[nt][2] - mn1);
            float p3 = ex2f(s[nt][3] - mn1);
            rs0 += p0 + p1;
            rs1 += p2 + p3;
            uint2 w0 = make_uint2(rnd_tf32f(p0), rnd_tf32f(p1));
            uint2 w1 = make_uint2(rnd_tf32f(p2), rnd_tf32f(p3));
            *(uint2*)&Ps[r0 * APAD + nt * 8 + tig * 2] = w0;
            *(uint2*)&Ps[(r0 + 8) * APAD + nt * 8 + tig * 2] = w1;
        }
        rs0 += __shfl_xor_sync(0xffffffffu, rs0, 1);
        rs0 += __shfl_xor_sync(0xffffffffu, rs0, 2);
        rs1 += __shfl_xor_sync(0xffffffffu, rs1, 1);
        rs1 += __shfl_xor_sync(0xffffffffu, rs1, 2);

        l0 = l0 * a0 + rs0;
        l1 = l1 * a1 + rs1;
        #pragma unroll
        for (int nt = 0; nt < 8; nt++) {
            o[nt][0] *= a0; o[nt][1] *= a0;
            o[nt][2] *= a1; o[nt][3] *= a1;
        }
        __syncwarp();   // P stores visible to all lanes of this warp

        // ---- O += P * V   (B-frag read from Vs[key][dh], bank 8*tig+gid, CF)
        #pragma unroll
        for (int ks = 0; ks < 8; ks++) {
            uint32_t pa0 = Ps[r0 * APAD + ks * 8 + tig];
            uint32_t pa1 = Ps[(r0 + 8) * APAD + ks * 8 + tig];
            uint32_t pa2 = Ps[r0 * APAD + ks * 8 + tig + 4];
            uint32_t pa3 = Ps[(r0 + 8) * APAD + ks * 8 + tig + 4];
            const uint32_t* vr0 = &Vs[(ks * 8 + tig) * KVPAD];
            const uint32_t* vr1 = &Vs[(ks * 8 + tig + 4) * KVPAD];
            #pragma unroll
            for (int nt = 0; nt < 8; nt++) {
                uint32_t b0 = rnd_tf32(vr0[nt * 8 + gid]);
                uint32_t b1 = rnd_tf32(vr1[nt * 8 + gid]);
                mma_tf32(o[nt][0], o[nt][1], o[nt][2], o[nt][3],
                         pa0, pa1, pa2, pa3, b0, b1);
            }
        }
    }

    // ---- epilogue: normalize and write context
    const float inv0 = 1.0f / l0;
    const float inv1 = 1.0f / l1;
    float* C0 = Ctx + ((long)b * SEQ + q0 + r0) * DM + h * DH;
    float* C1 = Ctx + ((long)b * SEQ + q0 + r0 + 8) * DM + h * DH;
    #pragma unroll
    for (int nt = 0; nt < 8; nt++) {
        const int col = nt * 8 + tig * 2;
        *(float2*)(C0 + col) = make_float2(o[nt][0] * inv0, o[nt][1] * inv0);
        *(float2*)(C1 + col) = make_float2(o[nt][2] * inv1, o[nt][3] * inv1);
    }
}

// ---------------------------------------------------------------------------
// kernel_launch  — inputs: q,k,v, Wq,bq, Wk,bk, Wv,bv, Wo,bo
// ---------------------------------------------------------------------------
extern "C" void kernel_launch(void* const* d_in, const int* in_sizes, int n_in,
                              void* d_out, int out_size)
{
    const float* q  = (const float*)d_in[0];
    const float* k  = (const float*)d_in[1];
    const float* v  = (const float*)d_in[2];
    const float* Wq = (const float*)d_in[3];
    const float* bq = (const float*)d_in[4];
    const float* Wk = (const float*)d_in[5];
    const float* bk = (const float*)d_in[6];
    const float* Wv = (const float*)d_in[7];
    const float* bv = (const float*)d_in[8];
    const float* Wo = (const float*)d_in[9];
    const float* bo = (const float*)d_in[10];
    float* out = (float*)d_out;

    float *pQ, *pK, *pV, *pC;
    cudaGetSymbolAddress((void**)&pQ, g_Q);
    cudaGetSymbolAddress((void**)&pK, g_K);
    cudaGetSymbolAddress((void**)&pV, g_V);
    cudaGetSymbolAddress((void**)&pC, g_C);

    cudaFuncSetAttribute(gemm_tf32_kernel,
                         cudaFuncAttributeMaxDynamicSharedMemorySize,
                         GEMM_SMEM_BYTES);
    cudaFuncSetAttribute(attn_mma_kernel,
                         cudaFuncAttributeMaxDynamicSharedMemorySize,
                         ATT_SMEM_BYTES);

    dim3 ggrid(DM / BN, MROWS / BM);     // (8, 32)
    gemm_tf32_kernel<<<ggrid, 256, GEMM_SMEM_BYTES>>>(q, Wq, bq, pQ);
    gemm_tf32_kernel<<<ggrid, 256, GEMM_SMEM_BYTES>>>(k, Wk, bk, pK);
    gemm_tf32_kernel<<<ggrid, 256, GEMM_SMEM_BYTES>>>(v, Wv, bv, pV);

    dim3 agrid(SEQ / 128, BATCH * NH);   // (16, 32)
    attn_mma_kernel<<<agrid, 256, ATT_SMEM_BYTES>>>(pQ, pK, pV, pC);

    gemm_tf32_kernel<<<ggrid, 256, GEMM_SMEM_BYTES>>>(pC, Wo, bo, out);
}

// round 11
// speedup vs baseline: 1.3007x; 1.0121x over previous
#include <cuda_runtime.h>
#include <cuda_bf16.h>
#include <math.h>
#include <cstdint>

// Problem constants
#define BATCH 2
#define SEQ 2048
#define DM 1024
#define NH 16
#define DH 64
#define MROWS (BATCH * SEQ)   // 4096

// ---------------------------------------------------------------------------
// Scratch (no cudaMalloc allowed)
// ---------------------------------------------------------------------------
__device__ __align__(256) float g_Q[MROWS * DM];
__device__ __align__(256) float g_K[MROWS * DM];
__device__ __align__(256) float g_V[MROWS * DM];
__device__ __align__(256) float g_C[MROWS * DM];

// ---------------------------------------------------------------------------
// Common helpers
// ---------------------------------------------------------------------------
__device__ __forceinline__ void mma_tf32(float& c0, float& c1, float& c2, float& c3,
                                         uint32_t a0, uint32_t a1, uint32_t a2, uint32_t a3,
                                         uint32_t b0, uint32_t b1) {
    asm volatile(
        "mma.sync.aligned.m16n8k8.row.col.f32.tf32.tf32.f32 "
        "{%0,%1,%2,%3}, {%4,%5,%6,%7}, {%8,%9}, {%0,%1,%2,%3};"
        : "+f"(c0), "+f"(c1), "+f"(c2), "+f"(c3)
        : "r"(a0), "r"(a1), "r"(a2), "r"(a3), "r"(b0), "r"(b1));
}

// fp32 -> tf32 round-to-nearest bit trick (HW truncates; +0x1000 completes RN)
__device__ __forceinline__ uint32_t rnd_tf32(uint32_t x) { return x + 0x1000u; }
__device__ __forceinline__ uint32_t rnd_tf32f(float x) { return __float_as_uint(x) + 0x1000u; }

__device__ __forceinline__ float ex2f(float x) {
    float y;
    asm("ex2.approx.f32 %0, %1;" : "=f"(y) : "f"(x));
    return y;
}

__device__ __forceinline__ uint32_t smem_u32(const void* p) {
    uint32_t a;
    asm("{ .reg .u64 t; cvta.to.shared.u64 t, %1; cvt.u32.u64 %0, t; }"
        : "=r"(a) : "l"(p));
    return a;
}

#define CP_ASYNC16(dst_u32, src_ptr) \
    asm volatile("cp.async.ca.shared.global [%0], [%1], 16;" \
                 :: "r"(dst_u32), "l"(src_ptr) : "memory")
#define CP_COMMIT()  asm volatile("cp.async.commit_group;" ::: "memory")
#define CP_WAIT0()   asm volatile("cp.async.wait_group 0;" ::: "memory")

// ---------------------------------------------------------------------------
// tf32 mma.sync GEMM: C[M,N] = A[M,K] * W[N,K]^T + bias[N]
// Tile 128x128x32, 256 threads, double-buffered smem, one barrier per chunk.
// outmode 0: write fp32 exact.
// outmode 1: write tf32-RN-rounded bits of (acc+bias)*oscale  (for Q/K/V —
//            consumed only by attention MMA; round-once semantics preserved).
// ---------------------------------------------------------------------------
#define BM 128
#define BN 128
#define BK 32
#define KPAD 36
#define NCHUNK (DM / BK)
#define ABUFU (BM * KPAD)
#define GEMM_SMEM_BYTES (4 * ABUFU * 4)

__global__ __launch_bounds__(256, 2) void gemm_tf32_kernel(
    const float* __restrict__ A, const float* __restrict__ W,
    const float* __restrict__ bias, float* __restrict__ C,
    int outmode, float oscale)
{
    extern __shared__ uint32_t gsm[];
    uint32_t* As0 = gsm;
    uint32_t* Bs0 = gsm + 2 * ABUFU;

    const int tid = threadIdx.x;
    const int wid = tid >> 5;
    const int lane = tid & 31;
    const int gid = lane >> 2;
    const int tig = lane & 3;

    const int wm = wid >> 2;
    const int wn = wid & 3;

    const int m0 = blockIdx.y * BM;
    const int n0 = blockIdx.x * BN;

    const int grow = tid >> 3;
    const int gcol = (tid & 7) * 4;

    const uint4* Ag = (const uint4*)(A + (long)(m0 + grow) * DM + gcol);
    const uint4* Wg = (const uint4*)(W + (long)(n0 + grow) * DM + gcol);

    float acc[4][4][4];
    #pragma unroll
    for (int i = 0; i < 4; i++)
        #pragma unroll
        for (int j = 0; j < 4; j++)
            #pragma unroll
            for (int c = 0; c < 4; c++) acc[i][j][c] = 0.0f;

    uint4 ra[4], rb[4];
    #pragma unroll
    for (int i = 0; i < 4; i++) {
        ra[i] = Ag[(long)i * 32 * (DM / 4)];
        rb[i] = Wg[(long)i * 32 * (DM / 4)];
    }
    #pragma unroll
    for (int i = 0; i < 4; i++) {
        uint4 va = make_uint4(rnd_tf32(ra[i].x), rnd_tf32(ra[i].y),
                              rnd_tf32(ra[i].z), rnd_tf32(ra[i].w));
        *(uint4*)&As0[(grow + i * 32) * KPAD + gcol] = va;
        uint4 vb = make_uint4(rnd_tf32(rb[i].x), rnd_tf32(rb[i].y),
                              rnd_tf32(rb[i].z), rnd_tf32(rb[i].w));
        *(uint4*)&Bs0[(grow + i * 32) * KPAD + gcol] = vb;
    }
    __syncthreads();

    for (int c = 0; c < NCHUNK; c++) {
        const uint32_t* As = As0 + (c & 1) * ABUFU;
        const uint32_t* Bs = Bs0 + (c & 1) * ABUFU;

        if (c + 1 < NCHUNK) {
            const uint4* an = Ag + (long)(c + 1) * (BK / 4);
            const uint4* bn = Wg + (long)(c + 1) * (BK / 4);
            #pragma unroll
            for (int i = 0; i < 4; i++) {
                ra[i] = an[(long)i * 32 * (DM / 4)];
                rb[i] = bn[(long)i * 32 * (DM / 4)];
            }
        }

        #pragma unroll
        for (int ks = 0; ks < 4; ks++) {
            const int k0 = ks * 8;
            uint32_t af[4][4], bf[4][2];
            #pragma unroll
            for (int mt = 0; mt < 4; mt++) {
                const int r = wm * 64 + mt * 16 + gid;
                af[mt][0] = As[r * KPAD + k0 + tig];
                af[mt][1] = As[(r + 8) * KPAD + k0 + tig];
                af[mt][2] = As[r * KPAD + k0 + tig + 4];
                af[mt][3] = As[(r + 8) * KPAD + k0 + tig + 4];
            }
            #pragma unroll
            for (int nt = 0; nt < 4; nt++) {
                const int r = wn * 32 + nt * 8 + gid;
                bf[nt][0] = Bs[r * KPAD + k0 + tig];
                bf[nt][1] = Bs[r * KPAD + k0 + tig + 4];
            }
            #pragma unroll
            for (int mt = 0; mt < 4; mt++)
                #pragma unroll
                for (int nt = 0; nt < 4; nt++)
                    mma_tf32(acc[mt][nt][0], acc[mt][nt][1],
                             acc[mt][nt][2], acc[mt][nt][3],
                             af[mt][0], af[mt][1], af[mt][2], af[mt][3],
                             bf[nt][0], bf[nt][1]);
        }

        if (c + 1 < NCHUNK) {
            uint32_t* An = As0 + ((c + 1) & 1) * ABUFU;
            uint32_t* Bn = Bs0 + ((c + 1) & 1) * ABUFU;
            #pragma unroll
            for (int i = 0; i < 4; i++) {
                uint4 va = make_uint4(rnd_tf32(ra[i].x), rnd_tf32(ra[i].y),
                                      rnd_tf32(ra[i].z), rnd_tf32(ra[i].w));
                *(uint4*)&An[(grow + i * 32) * KPAD + gcol] = va;
                uint4 vb = make_uint4(rnd_tf32(rb[i].x), rnd_tf32(rb[i].y),
                                      rnd_tf32(rb[i].z), rnd_tf32(rb[i].w));
                *(uint4*)&Bn[(grow + i * 32) * KPAD + gcol] = vb;
            }
        }
        __syncthreads();
    }

    #pragma unroll
    for (int mt = 0; mt < 4; mt++) {
        const int mrow = m0 + wm * 64 + mt * 16 + gid;
        #pragma unroll
        for (int nt = 0; nt < 4; nt++) {
            const int ncol = n0 + wn * 32 + nt * 8 + tig * 2;
            const float bx = bias[ncol];
            const float by = bias[ncol + 1];
            float v00 = acc[mt][nt][0] + bx, v01 = acc[mt][nt][1] + by;
            float v10 = acc[mt][nt][2] + bx, v11 = acc[mt][nt][3] + by;
            float2 w0, w1;
            if (outmode == 1) {
                w0 = make_float2(__uint_as_float(rnd_tf32f(v00 * oscale)),
                                 __uint_as_float(rnd_tf32f(v01 * oscale)));
                w1 = make_float2(__uint_as_float(rnd_tf32f(v10 * oscale)),
                                 __uint_as_float(rnd_tf32f(v11 * oscale)));
            } else {
                w0 = make_float2(v00, v01);
                w1 = make_float2(v10, v11);
            }
            *(float2*)(C + (long)mrow * DM + ncol) = w0;
            *(float2*)(C + (long)(mrow + 8) * DM + ncol) = w1;
        }
    }
}

// ---------------------------------------------------------------------------
// Tensor-core flash attention — R6 compute structure (8 warps x 16 q-rows)
// + cp.async double-buffered K/V + cp.async Q staging.
// Q/K/V arrive PRE-ROUNDED to tf32 (and Q pre-scaled by 1/8*log2e) from the
// projection GEMMs -> zero ALU on fragment paths, raw LDS feeds MMA.
// Layouts: Ps[128][68]; K,V [key][dh] stride 72:
//   QK B-frag:  Ks[(nt*8+gid)*72 + ks*8+tig(+4)]  -> bank 8*gid+tig  (CF)
//   PV B-frag:  Vs[(ks*8+tig)*72 + nt*8+gid]      -> bank 8*tig+gid  (CF)
// Loop: issue next-tile copies -> compute -> wait+barrier (stall-free wait).
// ---------------------------------------------------------------------------
#define APAD 68
#define KVPAD 72
#define TILEU (64 * KVPAD)
#define ATT_SMEM_U32 (128 * APAD + 4 * TILEU)
#define ATT_SMEM_BYTES (ATT_SMEM_U32 * 4)

__global__ __launch_bounds__(256, 2) void attn_mma_kernel(
    const float* __restrict__ Q, const float* __restrict__ K,
    const float* __restrict__ V, float* __restrict__ Ctx)
{
    extern __shared__ uint32_t sm[];
    uint32_t* Ps  = sm;                   // [128][APAD]
    uint32_t* KV0 = sm + 128 * APAD;      // 2 x (Ks[64][72], Vs[64][72])

    const int bh = blockIdx.y;
    const int b  = bh >> 4;
    const int h  = bh & 15;
    const int q0 = blockIdx.x * 128;

    const int tid  = threadIdx.x;
    const int wid  = tid >> 5;
    const int lane = tid & 31;
    const int gid  = lane >> 2;
    const int tig  = lane & 3;
    const int r0   = wid * 16 + gid;

    const float* Qg = Q + ((long)b * SEQ) * DM + h * DH;
    const float* Kg = K + ((long)b * SEQ) * DM + h * DH;
    const float* Vg = V + ((long)b * SEQ) * DM + h * DH;

    // cp.async staging coords: 4 threads per key row, 16 dh floats each
    const int tkey = tid & 63;
    const int dhb  = (tid >> 6) * 16;
    const uint32_t kv_base = smem_u32(KV0);
    const uint32_t ps_base = smem_u32(Ps);

    // ---- issue tile 0 K/V copies
    {
        const float* kp = Kg + (long)tkey * DM + dhb;
        const float* vp = Vg + (long)tkey * DM + dhb;
        const uint32_t kd = kv_base + (tkey * KVPAD + dhb) * 4;
        const uint32_t vd = kd + TILEU * 4;
        #pragma unroll
        for (int j = 0; j < 4; j++) {
            CP_ASYNC16(kd + j * 16, kp + j * 4);
            CP_ASYNC16(vd + j * 16, vp + j * 4);
        }
    }
    // ---- stage Q (pre-scaled, pre-rounded) straight into Ps via cp.async
    {
        const int row  = tid >> 1;
        const int col0 = (tid & 1) * 32;
        const float* qp = Qg + (long)(q0 + row) * DM + col0;
        const uint32_t qd = ps_base + (row * APAD + col0) * 4;
        #pragma unroll
        for (int j = 0; j < 8; j++)
            CP_ASYNC16(qd + j * 16, qp + j * 4);
    }
    CP_COMMIT();
    CP_WAIT0();
    __syncthreads();

    // ---- persistent Q fragments
    uint32_t qf[8][4];
    #pragma unroll
    for (int ks = 0; ks < 8; ks++) {
        qf[ks][0] = Ps[r0 * APAD + ks * 8 + tig];
        qf[ks][1] = Ps[(r0 + 8) * APAD + ks * 8 + tig];
        qf[ks][2] = Ps[r0 * APAD + ks * 8 + tig + 4];
        qf[ks][3] = Ps[(r0 + 8) * APAD + ks * 8 + tig + 4];
    }

    float o[8][4];
    #pragma unroll
    for (int nt = 0; nt < 8; nt++)
        #pragma unroll
        for (int c = 0; c < 4; c++) o[nt][c] = 0.0f;
    float mr0 = -INFINITY, mr1 = -INFINITY, l0 = 0.0f, l1 = 0.0f;

    const int NT = SEQ / 64;
    for (int it = 0; it < NT; it++) {
        // issue next tile's copies into the other buffer (overlaps compute)
        if (it + 1 < NT) {
            const long kr = (long)((it + 1) * 64 + tkey);
            const float* kp = Kg + kr * DM + dhb;
            const float* vp = Vg + kr * DM + dhb;
            const uint32_t kd = kv_base + (((it + 1) & 1) * 2 * TILEU
                                           + tkey * KVPAD + dhb) * 4;
            const uint32_t vd = kd + TILEU * 4;
            #pragma unroll
            for (int j = 0; j < 4; j++) {
                CP_ASYNC16(kd + j * 16, kp + j * 4);
                CP_ASYNC16(vd + j * 16, vp + j * 4);
            }
            CP_COMMIT();
        }

        const uint32_t* Ks = KV0 + (it & 1) * (2 * TILEU);
        const uint32_t* Vs = Ks + TILEU;

        // ---- S = Q * K^T  (per warp: 16 x 64)
        float s[8][4];
        #pragma unroll
        for (int nt = 0; nt < 8; nt++)
            #pragma unroll
            for (int c = 0; c < 4; c++) s[nt][c] = 0.0f;

        #pragma unroll
        for (int nt = 0; nt < 8; nt++) {
            const uint32_t* kb = &Ks[(nt * 8 + gid) * KVPAD];
            #pragma unroll
            for (int ks = 0; ks < 8; ks++) {
                uint32_t b0 = kb[ks * 8 + tig];
                uint32_t b1 = kb[ks * 8 + tig + 4];
                mma_tf32(s[nt][0], s[nt][1], s[nt][2], s[nt][3],
                         qf[ks][0], qf[ks][1], qf[ks][2], qf[ks][3], b0, b1);
            }
        }

        // ---- online softmax (log2 domain)
        float mt0 = -INFINITY, mt1 = -INFINITY;
        #pragma unroll
        for (int nt = 0; nt < 8; nt++) {
            mt0 = fmaxf(mt0, fmaxf(s[nt][0], s[nt][1]));
            mt1 = fmaxf(mt1, fmaxf(s[nt][2], s[nt][3]));
        }
        mt0 = fmaxf(mt0, __shfl_xor_sync(0xffffffffu, mt0, 1));
        mt0 = fmaxf(mt0, __shfl_xor_sync(0xffffffffu, mt0, 2));
        mt1 = fmaxf(mt1, __shfl_xor_sync(0xffffffffu, mt1, 1));
        mt1 = fmaxf(mt1, __shfl_xor_sync(0xffffffffu, mt1, 2));

        const float mn0 = fmaxf(mr0, mt0);
        const float mn1 = fmaxf(mr1, mt1);
        const float a0 = ex2f(mr0 - mn0);
        const float a1 = ex2f(mr1 - mn1);
        mr0 = mn0; mr1 = mn1;

        float rs0 = 0.0f, rs1 = 0.0f;
        #pragma unroll
        for (int nt = 0; nt < 8; nt++) {
            float p0 = ex2f(s[nt][0] - mn0);
            float p1 = ex2f(s[nt][1] - mn0);
            float p2 = ex2f(s[nt][2] - mn1);
            float p3 = ex2f(s[nt][3] - mn1);
            rs0 += p0 + p1;
            rs1 += p2 + p3;
            uint2 w0 = make_uint2(rnd_tf32f(p0), rnd_tf32f(p1));
            uint2 w1 = make_uint2(rnd_tf32f(p2), rnd_tf32f(p3));
            *(uint2*)&Ps[r0 * APAD + nt * 8 + tig * 2] = w0;
            *(uint2*)&Ps[(r0 + 8) * APAD + nt * 8 + tig * 2] = w1;
        }
        rs0 += __shfl_xor_sync(0xffffffffu, rs0, 1);
        rs0 += __shfl_xor_sync(0xffffffffu, rs0, 2);
        rs1 += __shfl_xor_sync(0xffffffffu, rs1, 1);
        rs1 += __shfl_xor_sync(0xffffffffu, rs1, 2);

        l0 = l0 * a0 + rs0;
        l1 = l1 * a1 + rs1;
        #pragma unroll
        for (int nt = 0; nt < 8; nt++) {
            o[nt][0] *= a0; o[nt][1] *= a0;
            o[nt][2] *= a1; o[nt][3] *= a1;
        }
        __syncwarp();   // P stores visible to all lanes of this warp

        // ---- O += P * V   (B-frag from Vs[key][dh], bank 8*tig+gid, CF)
        #pragma unroll
        for (int ks = 0; ks < 8; ks++) {
            uint32_t pa0 = Ps[r0 * APAD + ks * 8 + tig];
            uint32_t pa1 = Ps[(r0 + 8) * APAD + ks * 8 + tig];
            uint32_t pa2 = Ps[r0 * APAD + ks * 8 + tig + 4];
            uint32_t pa3 = Ps[(r0 + 8) * APAD + ks * 8 + tig + 4];
            const uint32_t* vr0 = &Vs[(ks * 8 + tig) * KVPAD];
            const uint32_t* vr1 = &Vs[(ks * 8 + tig + 4) * KVPAD];
            #pragma unroll
            for (int nt = 0; nt < 8; nt++) {
                uint32_t b0 = vr0[nt * 8 + gid];
                uint32_t b1 = vr1[nt * 8 + gid];
                mma_tf32(o[nt][0], o[nt][1], o[nt][2], o[nt][3],
                         pa0, pa1, pa2, pa3, b0, b1);
            }
        }

        // next tile's copies have had the whole compute phase to land
        CP_WAIT0();
        __syncthreads();
    }

    // ---- epilogue: normalize and write context
    const float inv0 = 1.0f / l0;
    const float inv1 = 1.0f / l1;
    float* C0 = Ctx + ((long)b * SEQ + q0 + r0) * DM + h * DH;
    float* C1 = Ctx + ((long)b * SEQ + q0 + r0 + 8) * DM + h * DH;
    #pragma unroll
    for (int nt = 0; nt < 8; nt++) {
        const int col = nt * 8 + tig * 2;
        *(float2*)(C0 + col) = make_float2(o[nt][0] * inv0, o[nt][1] * inv0);
        *(float2*)(C1 + col) = make_float2(o[nt][2] * inv1, o[nt][3] * inv1);
    }
}

// ---------------------------------------------------------------------------
// kernel_launch  — inputs: q,k,v, Wq,bq, Wk,bk, Wv,bv, Wo,bo
// ---------------------------------------------------------------------------
extern "C" void kernel_launch(void* const* d_in, const int* in_sizes, int n_in,
                              void* d_out, int out_size)
{
    const float* q  = (const float*)d_in[0];
    const float* k  = (const float*)d_in[1];
    const float* v  = (const float*)d_in[2];
    const float* Wq = (const float*)d_in[3];
    const float* bq = (const float*)d_in[4];
    const float* Wk = (const float*)d_in[5];
    const float* bk = (const float*)d_in[6];
    const float* Wv = (const float*)d_in[7];
    const float* bv = (const float*)d_in[8];
    const float* Wo = (const float*)d_in[9];
    const float* bo = (const float*)d_in[10];
    float* out = (float*)d_out;

    float *pQ, *pK, *pV, *pC;
    cudaGetSymbolAddress((void**)&pQ, g_Q);
    cudaGetSymbolAddress((void**)&pK, g_K);
    cudaGetSymbolAddress((void**)&pV, g_V);
    cudaGetSymbolAddress((void**)&pC, g_C);

    cudaFuncSetAttribute(gemm_tf32_kernel,
                         cudaFuncAttributeMaxDynamicSharedMemorySize,
                         GEMM_SMEM_BYTES);
    cudaFuncSetAttribute(attn_mma_kernel,
                         cudaFuncAttributeMaxDynamicSharedMemorySize,
                         ATT_SMEM_BYTES);

    const float cf = 0.125f * 1.44269504088896f;   // 1/sqrt(64) * log2(e)

    dim3 ggrid(DM / BN, MROWS / BM);     // (8, 32)
    // Q/K/V projections write pre-rounded tf32 (Q additionally pre-scaled)
    gemm_tf32_kernel<<<ggrid, 256, GEMM_SMEM_BYTES>>>(q, Wq, bq, pQ, 1, cf);
    gemm_tf32_kernel<<<ggrid, 256, GEMM_SMEM_BYTES>>>(k, Wk, bk, pK, 1, 1.0f);
    gemm_tf32_kernel<<<ggrid, 256, GEMM_SMEM_BYTES>>>(v, Wv, bv, pV, 1, 1.0f);

    dim3 agrid(SEQ / 128, BATCH * NH);   // (16, 32)
    attn_mma_kernel<<<agrid, 256, ATT_SMEM_BYTES>>>(pQ, pK, pV, pC);

    // final projection: exact fp32 output
    gemm_tf32_kernel<<<ggrid, 256, GEMM_SMEM_BYTES>>>(pC, Wo, bo, out, 0, 1.0f);
}

// round 13
// speedup vs baseline: 1.4451x; 1.1110x over previous
#include <cuda_runtime.h>
#include <cuda_bf16.h>
#include <math.h>
#include <cstdint>

// Problem constants
#define BATCH 2
#define SEQ 2048
#define DM 1024
#define NH 16
#define DH 64
#define MROWS (BATCH * SEQ)   // 4096

// ---------------------------------------------------------------------------
// Scratch (no cudaMalloc allowed)
// ---------------------------------------------------------------------------
__device__ __align__(256) float g_Q[MROWS * DM];
__device__ __align__(256) float g_K[MROWS * DM];
__device__ __align__(256) float g_V[MROWS * DM];
__device__ __align__(256) float g_C[MROWS * DM];

// ---------------------------------------------------------------------------
// Common helpers
// ---------------------------------------------------------------------------
__device__ __forceinline__ void mma_tf32(float& c0, float& c1, float& c2, float& c3,
                                         uint32_t a0, uint32_t a1, uint32_t a2, uint32_t a3,
                                         uint32_t b0, uint32_t b1) {
    asm volatile(
        "mma.sync.aligned.m16n8k8.row.col.f32.tf32.tf32.f32 "
        "{%0,%1,%2,%3}, {%4,%5,%6,%7}, {%8,%9}, {%0,%1,%2,%3};"
        : "+f"(c0), "+f"(c1), "+f"(c2), "+f"(c3)
        : "r"(a0), "r"(a1), "r"(a2), "r"(a3), "r"(b0), "r"(b1));
}

// fp32 -> tf32 round-to-nearest bit trick (HW truncates; +0x1000 completes RN)
__device__ __forceinline__ uint32_t rnd_tf32(uint32_t x) { return x + 0x1000u; }
__device__ __forceinline__ uint32_t rnd_tf32f(float x) { return __float_as_uint(x) + 0x1000u; }

__device__ __forceinline__ float ex2f(float x) {
    float y;
    asm("ex2.approx.f32 %0, %1;" : "=f"(y) : "f"(x));
    return y;
}

// ---------------------------------------------------------------------------
// tf32 mma.sync GEMM body: C[M,N] = A[M,K] * W[N,K]^T + bias[N]
// Tile 128x128x32, 256 threads, double-buffered smem, one barrier per chunk.
// outmode 0: write fp32 exact.
// outmode 1: write tf32-RN-rounded bits of (acc+bias)*oscale (Q/K/V — consumed
//            only by attention MMA; round-once semantics preserved).
// ---------------------------------------------------------------------------
#define BM 128
#define BN 128
#define BK 32
#define KPAD 36
#define NCHUNK (DM / BK)
#define ABUFU (BM * KPAD)
#define GEMM_SMEM_BYTES (4 * ABUFU * 4)

__device__ __forceinline__ void gemm_body(
    const float* __restrict__ A, const float* __restrict__ W,
    const float* __restrict__ bias, float* __restrict__ C,
    int outmode, float oscale, uint32_t* gsm)
{
    uint32_t* As0 = gsm;
    uint32_t* Bs0 = gsm + 2 * ABUFU;

    const int tid = threadIdx.x;
    const int wid = tid >> 5;
    const int lane = tid & 31;
    const int gid = lane >> 2;
    const int tig = lane & 3;

    const int wm = wid >> 2;
    const int wn = wid & 3;

    const int m0 = blockIdx.y * BM;
    const int n0 = blockIdx.x * BN;

    const int grow = tid >> 3;
    const int gcol = (tid & 7) * 4;

    const uint4* Ag = (const uint4*)(A + (long)(m0 + grow) * DM + gcol);
    const uint4* Wg = (const uint4*)(W + (long)(n0 + grow) * DM + gcol);

    float acc[4][4][4];
    #pragma unroll
    for (int i = 0; i < 4; i++)
        #pragma unroll
        for (int j = 0; j < 4; j++)
            #pragma unroll
            for (int c = 0; c < 4; c++) acc[i][j][c] = 0.0f;

    uint4 ra[4], rb[4];
    #pragma unroll
    for (int i = 0; i < 4; i++) {
        ra[i] = Ag[(long)i * 32 * (DM / 4)];
        rb[i] = Wg[(long)i * 32 * (DM / 4)];
    }
    #pragma unroll
    for (int i = 0; i < 4; i++) {
        uint4 va = make_uint4(rnd_tf32(ra[i].x), rnd_tf32(ra[i].y),
                              rnd_tf32(ra[i].z), rnd_tf32(ra[i].w));
        *(uint4*)&As0[(grow + i * 32) * KPAD + gcol] = va;
        uint4 vb = make_uint4(rnd_tf32(rb[i].x), rnd_tf32(rb[i].y),
                              rnd_tf32(rb[i].z), rnd_tf32(rb[i].w));
        *(uint4*)&Bs0[(grow + i * 32) * KPAD + gcol] = vb;
    }
    __syncthreads();

    for (int c = 0; c < NCHUNK; c++) {
        const uint32_t* As = As0 + (c & 1) * ABUFU;
        const uint32_t* Bs = Bs0 + (c & 1) * ABUFU;

        if (c + 1 < NCHUNK) {
            const uint4* an = Ag + (long)(c + 1) * (BK / 4);
            const uint4* bn = Wg + (long)(c + 1) * (BK / 4);
            #pragma unroll
            for (int i = 0; i < 4; i++) {
                ra[i] = an[(long)i * 32 * (DM / 4)];
                rb[i] = bn[(long)i * 32 * (DM / 4)];
            }
        }

        #pragma unroll
        for (int ks = 0; ks < 4; ks++) {
            const int k0 = ks * 8;
            uint32_t af[4][4], bf[4][2];
            #pragma unroll
            for (int mt = 0; mt < 4; mt++) {
                const int r = wm * 64 + mt * 16 + gid;
                af[mt][0] = As[r * KPAD + k0 + tig];
                af[mt][1] = As[(r + 8) * KPAD + k0 + tig];
                af[mt][2] = As[r * KPAD + k0 + tig + 4];
                af[mt][3] = As[(r + 8) * KPAD + k0 + tig + 4];
            }
            #pragma unroll
            for (int nt = 0; nt < 4; nt++) {
                const int r = wn * 32 + nt * 8 + gid;
                bf[nt][0] = Bs[r * KPAD + k0 + tig];
                bf[nt][1] = Bs[r * KPAD + k0 + tig + 4];
            }
            #pragma unroll
            for (int mt = 0; mt < 4; mt++)
                #pragma unroll
                for (int nt = 0; nt < 4; nt++)
                    mma_tf32(acc[mt][nt][0], acc[mt][nt][1],
                             acc[mt][nt][2], acc[mt][nt][3],
                             af[mt][0], af[mt][1], af[mt][2], af[mt][3],
                             bf[nt][0], bf[nt][1]);
        }

        if (c + 1 < NCHUNK) {
            uint32_t* An = As0 + ((c + 1) & 1) * ABUFU;
            uint32_t* Bn = Bs0 + ((c + 1) & 1) * ABUFU;
            #pragma unroll
            for (int i = 0; i < 4; i++) {
                uint4 va = make_uint4(rnd_tf32(ra[i].x), rnd_tf32(ra[i].y),
                                      rnd_tf32(ra[i].z), rnd_tf32(ra[i].w));
                *(uint4*)&An[(grow + i * 32) * KPAD + gcol] = va;
                uint4 vb = make_uint4(rnd_tf32(rb[i].x), rnd_tf32(rb[i].y),
                                      rnd_tf32(rb[i].z), rnd_tf32(rb[i].w));
                *(uint4*)&Bn[(grow + i * 32) * KPAD + gcol] = vb;
            }
        }
        __syncthreads();
    }

    #pragma unroll
    for (int mt = 0; mt < 4; mt++) {
        const int mrow = m0 + wm * 64 + mt * 16 + gid;
        #pragma unroll
        for (int nt = 0; nt < 4; nt++) {
            const int ncol = n0 + wn * 32 + nt * 8 + tig * 2;
            const float bx = bias[ncol];
            const float by = bias[ncol + 1];
            float v00 = acc[mt][nt][0] + bx, v01 = acc[mt][nt][1] + by;
            float v10 = acc[mt][nt][2] + bx, v11 = acc[mt][nt][3] + by;
            float2 w0, w1;
            if (outmode == 1) {
                w0 = make_float2(__uint_as_float(rnd_tf32f(v00 * oscale)),
                                 __uint_as_float(rnd_tf32f(v01 * oscale)));
                w1 = make_float2(__uint_as_float(rnd_tf32f(v10 * oscale)),
                                 __uint_as_float(rnd_tf32f(v11 * oscale)));
            } else {
                w0 = make_float2(v00, v01);
                w1 = make_float2(v10, v11);
            }
            *(float2*)(C + (long)mrow * DM + ncol) = w0;
            *(float2*)(C + (long)(mrow + 8) * DM + ncol) = w1;
        }
    }
}

// Merged QKV projection: blockIdx.z selects (input, W, bias, output, scale).
// 768 CTAs in one launch -> 2.6 packed waves instead of 3 x 0.86-wave tails.
__global__ __launch_bounds__(256, 2) void qkv_gemm_kernel(
    const float* __restrict__ q, const float* __restrict__ k,
    const float* __restrict__ v,
    const float* __restrict__ Wq, const float* __restrict__ bq,
    const float* __restrict__ Wk, const float* __restrict__ bk,
    const float* __restrict__ Wv, const float* __restrict__ bv,
    float* __restrict__ oQ, float* __restrict__ oK, float* __restrict__ oV,
    float qscale)
{
    extern __shared__ uint32_t gsm[];
    const int z = blockIdx.z;
    const float* A    = (z == 0) ? q  : (z == 1) ? k  : v;
    const float* W    = (z == 0) ? Wq : (z == 1) ? Wk : Wv;
    const float* bias = (z == 0) ? bq : (z == 1) ? bk : bv;
    float*       C    = (z == 0) ? oQ : (z == 1) ? oK : oV;
    const float os    = (z == 0) ? qscale : 1.0f;
    gemm_body(A, W, bias, C, 1, os, gsm);
}

// Output projection (exact fp32 epilogue).
__global__ __launch_bounds__(256, 2) void gemm_tf32_kernel(
    const float* __restrict__ A, const float* __restrict__ W,
    const float* __restrict__ bias, float* __restrict__ C)
{
    extern __shared__ uint32_t gsm[];
    gemm_body(A, W, bias, C, 0, 1.0f, gsm);
}

// ---------------------------------------------------------------------------
// Tensor-core flash attention — exact R6 compute structure (8 warps x 16
// q-rows, 256 threads, single-buffer K/V, two barriers per tile).
// Staging fix vs R6: thread t covers key=t&63, dh=(t>>6)*16..+15.
//   K STS.128 -> phase quad-banks (17*tkey + dhb/4) mod 8 distinct  (CF)
//   V transposed scalar STS -> bank = tkey mod 32                   (CF;
//     R6's mapping was 4-way conflicted here)
// Inputs pre-rounded (Q pre-scaled) by projection GEMMs -> staging is a pure
// copy, fragment paths feed MMA raw. All strides APAD=68 (CF frag reads).
// ---------------------------------------------------------------------------
#define APAD 68
#define ATT_SMEM_U32 (256 * APAD)        // Ps 128 rows + Ks 64 + Vt 64
#define ATT_SMEM_BYTES (ATT_SMEM_U32 * 4)

__global__ __launch_bounds__(256, 2) void attn_mma_kernel(
    const float* __restrict__ Q, const float* __restrict__ K,
    const float* __restrict__ V, float* __restrict__ Ctx)
{
    extern __shared__ uint32_t sm[];
    uint32_t* Ps = sm;                    // [128][APAD]
    uint32_t* Ks = sm + 128 * APAD;       // [64][APAD]  (K[key][dh])
    uint32_t* Vt = Ks + 64 * APAD;        // [64][APAD]  (V^T[dh][key])

    const int bh = blockIdx.y;
    const int b  = bh >> 4;
    const int h  = bh & 15;
    const int q0 = blockIdx.x * 128;

    const int tid  = threadIdx.x;
    const int wid  = tid >> 5;
    const int lane = tid & 31;
    const int gid  = lane >> 2;
    const int tig  = lane & 3;
    const int r0   = wid * 16 + gid;

    const float* Qg = Q + ((long)b * SEQ) * DM + h * DH;
    const float* Kg = K + ((long)b * SEQ) * DM + h * DH;
    const float* Vg = V + ((long)b * SEQ) * DM + h * DH;

    // staging coords: 4 threads per key row, 16 dh floats each
    const int tkey = tid & 63;
    const int dhb  = (tid >> 6) * 16;

    // ---- stage Q (pre-scaled, pre-rounded): pure copy
    {
        const int row  = tid >> 1;
        const int col0 = (tid & 1) * 32;
        const uint4* qp = (const uint4*)(Qg + (long)(q0 + row) * DM + col0);
        #pragma unroll
        for (int j = 0; j < 8; j++)
            *(uint4*)&Ps[row * APAD + col0 + j * 4] = qp[j];
    }
    __syncthreads();

    // ---- persistent Q fragments
    uint32_t qf[8][4];
    #pragma unroll
    for (int ks = 0; ks < 8; ks++) {
        qf[ks][0] = Ps[r0 * APAD + ks * 8 + tig];
        qf[ks][1] = Ps[(r0 + 8) * APAD + ks * 8 + tig];
        qf[ks][2] = Ps[r0 * APAD + ks * 8 + tig + 4];
        qf[ks][3] = Ps[(r0 + 8) * APAD + ks * 8 + tig + 4];
    }

    float o[8][4];
    #pragma unroll
    for (int nt = 0; nt < 8; nt++)
        #pragma unroll
        for (int c = 0; c < 4; c++) o[nt][c] = 0.0f;
    float mr0 = -INFINITY, mr1 = -INFINITY, l0 = 0.0f, l1 = 0.0f;

    const int NT = SEQ / 64;
    for (int it = 0; it < NT; it++) {
        __syncthreads();   // prior-tile fragment reads complete

        // ---- stage K tile [key][dh] + V^T tile [dh][key] (pure copy, CF)
        {
            const long kr = (long)(it * 64 + tkey);
            const uint4* kp = (const uint4*)(Kg + kr * DM + dhb);
            const uint4* vp = (const uint4*)(Vg + kr * DM + dhb);
            #pragma unroll
            for (int j = 0; j < 4; j++) {
                *(uint4*)&Ks[tkey * APAD + dhb + 4 * j] = kp[j];
                uint4 vv = vp[j];
                const int dv = dhb + 4 * j;
                Vt[(dv + 0) * APAD + tkey] = vv.x;
                Vt[(dv + 1) * APAD + tkey] = vv.y;
                Vt[(dv + 2) * APAD + tkey] = vv.z;
                Vt[(dv + 3) * APAD + tkey] = vv.w;
            }
        }
        __syncthreads();

        // ---- S = Q * K^T  (per warp: 16 x 64)
        float s[8][4];
        #pragma unroll
        for (int nt = 0; nt < 8; nt++)
            #pragma unroll
            for (int c = 0; c < 4; c++) s[nt][c] = 0.0f;

        #pragma unroll
        for (int nt = 0; nt < 8; nt++) {
            const uint32_t* kb = &Ks[(nt * 8 + gid) * APAD];
            #pragma unroll
            for (int ks = 0; ks < 8; ks++) {
                uint32_t b0 = kb[ks * 8 + tig];
                uint32_t b1 = kb[ks * 8 + tig + 4];
                mma_tf32(s[nt][0], s[nt][1], s[nt][2], s[nt][3],
                         qf[ks][0], qf[ks][1], qf[ks][2], qf[ks][3], b0, b1);
            }
        }

        // ---- online softmax (log2 domain)
        float mt0 = -INFINITY, mt1 = -INFINITY;
        #pragma unroll
        for (int nt = 0; nt < 8; nt++) {
            mt0 = fmaxf(mt0, fmaxf(s[nt][0], s[nt][1]));
            mt1 = fmaxf(mt1, fmaxf(s[nt][2], s[nt][3]));
        }
        mt0 = fmaxf(mt0, __shfl_xor_sync(0xffffffffu, mt0, 1));
        mt0 = fmaxf(mt0, __shfl_xor_sync(0xffffffffu, mt0, 2));
        mt1 = fmaxf(mt1, __shfl_xor_sync(0xffffffffu, mt1, 1));
        mt1 = fmaxf(mt1, __shfl_xor_sync(0xffffffffu, mt1, 2));

        const float mn0 = fmaxf(mr0, mt0);
        const float mn1 = fmaxf(mr1, mt1);
        const float a0 = ex2f(mr0 - mn0);
        const float a1 = ex2f(mr1 - mn1);
        mr0 = mn0; mr1 = mn1;

        float rs0 = 0.0f, rs1 = 0.0f;
        #pragma unroll
        for (int nt = 0; nt < 8; nt++) {
            float p0 = ex2f(s[nt][0] - mn0);
            float p1 = ex2f(s[nt][1] - mn0);
            float p2 = ex2f(s[nt][2] - mn1);
            float p3 = ex2f(s[nt][3] - mn1);
            rs0 += p0 + p1;
            rs1 += p2 + p3;
            uint2 w0 = make_uint2(rnd_tf32f(p0), rnd_tf32f(p1));
            uint2 w1 = make_uint2(rnd_tf32f(p2), rnd_tf32f(p3));
            *(uint2*)&Ps[r0 * APAD + nt * 8 + tig * 2] = w0;
            *(uint2*)&Ps[(r0 + 8) * APAD + nt * 8 + tig * 2] = w1;
        }
        rs0 += __shfl_xor_sync(0xffffffffu, rs0, 1);
        rs0 += __shfl_xor_sync(0xffffffffu, rs0, 2);
        rs1 += __shfl_xor_sync(0xffffffffu, rs1, 1);
        rs1 += __shfl_xor_sync(0xffffffffu, rs1, 2);

        l0 = l0 * a0 + rs0;
        l1 = l1 * a1 + rs1;
        #pragma unroll
        for (int nt = 0; nt < 8; nt++) {
            o[nt][0] *= a0; o[nt][1] *= a0;
            o[nt][2] *= a1; o[nt][3] *= a1;
        }
        __syncwarp();   // P stores visible to all lanes of this warp

        // ---- O += P * V  (B-frag from Vt[dh][key], bank 4*gid+tig, CF)
        #pragma unroll
        for (int ks = 0; ks < 8; ks++) {
            uint32_t pa0 = Ps[r0 * APAD + ks * 8 + tig];
            uint32_t pa1 = Ps[(r0 + 8) * APAD + ks * 8 + tig];
            uint32_t pa2 = Ps[r0 * APAD + ks * 8 + tig + 4];
            uint32_t pa3 = Ps[(r0 + 8) * APAD + ks * 8 + tig + 4];
            #pragma unroll
            for (int nt = 0; nt < 8; nt++) {
                const uint32_t* vb = &Vt[(nt * 8 + gid) * APAD];
                uint32_t b0 = vb[ks * 8 + tig];
                uint32_t b1 = vb[ks * 8 + tig + 4];
                mma_tf32(o[nt][0], o[nt][1], o[nt][2], o[nt][3],
                         pa0, pa1, pa2, pa3, b0, b1);
            }
        }
    }

    // ---- epilogue: normalize and write context
    const float inv0 = 1.0f / l0;
    const float inv1 = 1.0f / l1;
    float* C0 = Ctx + ((long)b * SEQ + q0 + r0) * DM + h * DH;
    float* C1 = Ctx + ((long)b * SEQ + q0 + r0 + 8) * DM + h * DH;
    #pragma unroll
    for (int nt = 0; nt < 8; nt++) {
        const int col = nt * 8 + tig * 2;
        *(float2*)(C0 + col) = make_float2(o[nt][0] * inv0, o[nt][1] * inv0);
        *(float2*)(C1 + col) = make_float2(o[nt][2] * inv1, o[nt][3] * inv1);
    }
}

// ---------------------------------------------------------------------------
// kernel_launch  — inputs: q,k,v, Wq,bq, Wk,bk, Wv,bv, Wo,bo
// ---------------------------------------------------------------------------
extern "C" void kernel_launch(void* const* d_in, const int* in_sizes, int n_in,
                              void* d_out, int out_size)
{
    const float* q  = (const float*)d_in[0];
    const float* k  = (const float*)d_in[1];
    const float* v  = (const float*)d_in[2];
    const float* Wq = (const float*)d_in[3];
    const float* bq = (const float*)d_in[4];
    const float* Wk = (const float*)d_in[5];
    const float* bk = (const float*)d_in[6];
    const float* Wv = (const float*)d_in[7];
    const float* bv = (const float*)d_in[8];
    const float* Wo = (const float*)d_in[9];
    const float* bo = (const float*)d_in[10];
    float* out = (float*)d_out;

    float *pQ, *pK, *pV, *pC;
    cudaGetSymbolAddress((void**)&pQ, g_Q);
    cudaGetSymbolAddress((void**)&pK, g_K);
    cudaGetSymbolAddress((void**)&pV, g_V);
    cudaGetSymbolAddress((void**)&pC, g_C);

    cudaFuncSetAttribute(qkv_gemm_kernel,
                         cudaFuncAttributeMaxDynamicSharedMemorySize,
                         GEMM_SMEM_BYTES);
    cudaFuncSetAttribute(gemm_tf32_kernel,
                         cudaFuncAttributeMaxDynamicSharedMemorySize,
                         GEMM_SMEM_BYTES);
    cudaFuncSetAttribute(attn_mma_kernel,
                         cudaFuncAttributeMaxDynamicSharedMemorySize,
                         ATT_SMEM_BYTES);

    const float cf = 0.125f * 1.44269504088896f;   // 1/sqrt(64) * log2(e)

    // merged Q/K/V projections (pre-rounded tf32 outputs; Q pre-scaled)
    dim3 qkvgrid(DM / BN, MROWS / BM, 3);   // (8, 32, 3)
    qkv_gemm_kernel<<<qkvgrid, 256, GEMM_SMEM_BYTES>>>(
        q, k, v, Wq, bq, Wk, bk, Wv, bv, pQ, pK, pV, cf);

    dim3 agrid(SEQ / 128, BATCH * NH);      // (16, 32)
    attn_mma_kernel<<<agrid, 256, ATT_SMEM_BYTES>>>(pQ, pK, pV, pC);

    // final projection: exact fp32 output
    dim3 ggrid(DM / BN, MROWS / BM);        // (8, 32)
    gemm_tf32_kernel<<<ggrid, 256, GEMM_SMEM_BYTES>>>(pC, Wo, bo, out);
}

// round 14
// speedup vs baseline: 1.4528x; 1.0053x over previous
#include <cuda_runtime.h>
#include <cuda_bf16.h>
#include <math.h>
#include <cstdint>

// Problem constants
#define BATCH 2
#define SEQ 2048
#define DM 1024
#define NH 16
#define DH 64
#define MROWS (BATCH * SEQ)   // 4096

// ---------------------------------------------------------------------------
// Scratch (no cudaMalloc allowed)
// ---------------------------------------------------------------------------
__device__ __align__(256) float g_Q[MROWS * DM];
__device__ __align__(256) float g_K[MROWS * DM];
__device__ __align__(256) float g_V[MROWS * DM];
__device__ __align__(256) float g_C[MROWS * DM];

// ---------------------------------------------------------------------------
// Common helpers
// ---------------------------------------------------------------------------
__device__ __forceinline__ void mma_tf32(float& c0, float& c1, float& c2, float& c3,
                                         uint32_t a0, uint32_t a1, uint32_t a2, uint32_t a3,
                                         uint32_t b0, uint32_t b1) {
    asm volatile(
        "mma.sync.aligned.m16n8k8.row.col.f32.tf32.tf32.f32 "
        "{%0,%1,%2,%3}, {%4,%5,%6,%7}, {%8,%9}, {%0,%1,%2,%3};"
        : "+f"(c0), "+f"(c1), "+f"(c2), "+f"(c3)
        : "r"(a0), "r"(a1), "r"(a2), "r"(a3), "r"(b0), "r"(b1));
}

// fp32 -> tf32 round-to-nearest bit trick (HW truncates; +0x1000 completes RN)
__device__ __forceinline__ uint32_t rnd_tf32(uint32_t x) { return x + 0x1000u; }
__device__ __forceinline__ uint32_t rnd_tf32f(float x) { return __float_as_uint(x) + 0x1000u; }

__device__ __forceinline__ float ex2f(float x) {
    float y;
    asm("ex2.approx.f32 %0, %1;" : "=f"(y) : "f"(x));
    return y;
}

// ---------------------------------------------------------------------------
// tf32 mma.sync GEMM body: C[M,N] = A[M,K] * W[N,K]^T + bias[N]
// Tile 128x128x32, 256 threads, double-buffered smem, one barrier per chunk.
// outmode 0: write fp32 exact.
// outmode 1: write tf32-RN-rounded bits of (acc+bias)*oscale (Q/K/V — consumed
//            only by attention MMA; round-once semantics preserved).
// ---------------------------------------------------------------------------
#define BM 128
#define BN 128
#define BK 32
#define KPAD 36
#define NCHUNK (DM / BK)
#define ABUFU (BM * KPAD)
#define GEMM_SMEM_BYTES (4 * ABUFU * 4)

__device__ __forceinline__ void gemm_body(
    const float* __restrict__ A, const float* __restrict__ W,
    const float* __restrict__ bias, float* __restrict__ C,
    int outmode, float oscale, uint32_t* gsm)
{
    uint32_t* As0 = gsm;
    uint32_t* Bs0 = gsm + 2 * ABUFU;

    const int tid = threadIdx.x;
    const int wid = tid >> 5;
    const int lane = tid & 31;
    const int gid = lane >> 2;
    const int tig = lane & 3;

    const int wm = wid >> 2;
    const int wn = wid & 3;

    const int m0 = blockIdx.y * BM;
    const int n0 = blockIdx.x * BN;

    const int grow = tid >> 3;
    const int gcol = (tid & 7) * 4;

    const uint4* Ag = (const uint4*)(A + (long)(m0 + grow) * DM + gcol);
    const uint4* Wg = (const uint4*)(W + (long)(n0 + grow) * DM + gcol);

    float acc[4][4][4];
    #pragma unroll
    for (int i = 0; i < 4; i++)
        #pragma unroll
        for (int j = 0; j < 4; j++)
            #pragma unroll
            for (int c = 0; c < 4; c++) acc[i][j][c] = 0.0f;

    uint4 ra[4], rb[4];
    #pragma unroll
    for (int i = 0; i < 4; i++) {
        ra[i] = Ag[(long)i * 32 * (DM / 4)];
        rb[i] = Wg[(long)i * 32 * (DM / 4)];
    }
    #pragma unroll
    for (int i = 0; i < 4; i++) {
        uint4 va = make_uint4(rnd_tf32(ra[i].x), rnd_tf32(ra[i].y),
                              rnd_tf32(ra[i].z), rnd_tf32(ra[i].w));
        *(uint4*)&As0[(grow + i * 32) * KPAD + gcol] = va;
        uint4 vb = make_uint4(rnd_tf32(rb[i].x), rnd_tf32(rb[i].y),
                              rnd_tf32(rb[i].z), rnd_tf32(rb[i].w));
        *(uint4*)&Bs0[(grow + i * 32) * KPAD + gcol] = vb;
    }
    __syncthreads();

    for (int c = 0; c < NCHUNK; c++) {
        const uint32_t* As = As0 + (c & 1) * ABUFU;
        const uint32_t* Bs = Bs0 + (c & 1) * ABUFU;

        if (c + 1 < NCHUNK) {
            const uint4* an = Ag + (long)(c + 1) * (BK / 4);
            const uint4* bn = Wg + (long)(c + 1) * (BK / 4);
            #pragma unroll
            for (int i = 0; i < 4; i++) {
                ra[i] = an[(long)i * 32 * (DM / 4)];
                rb[i] = bn[(long)i * 32 * (DM / 4)];
            }
        }

        #pragma unroll
        for (int ks = 0; ks < 4; ks++) {
            const int k0 = ks * 8;
            uint32_t af[4][4], bf[4][2];
            #pragma unroll
            for (int mt = 0; mt < 4; mt++) {
                const int r = wm * 64 + mt * 16 + gid;
                af[mt][0] = As[r * KPAD + k0 + tig];
                af[mt][1] = As[(r + 8) * KPAD + k0 + tig];
                af[mt][2] = As[r * KPAD + k0 + tig + 4];
                af[mt][3] = As[(r + 8) * KPAD + k0 + tig + 4];
            }
            #pragma unroll
            for (int nt = 0; nt < 4; nt++) {
                const int r = wn * 32 + nt * 8 + gid;
                bf[nt][0] = Bs[r * KPAD + k0 + tig];
                bf[nt][1] = Bs[r * KPAD + k0 + tig + 4];
            }
            #pragma unroll
            for (int mt = 0; mt < 4; mt++)
                #pragma unroll
                for (int nt = 0; nt < 4; nt++)
                    mma_tf32(acc[mt][nt][0], acc[mt][nt][1],
                             acc[mt][nt][2], acc[mt][nt][3],
                             af[mt][0], af[mt][1], af[mt][2], af[mt][3],
                             bf[nt][0], bf[nt][1]);
        }

        if (c + 1 < NCHUNK) {
            uint32_t* An = As0 + ((c + 1) & 1) * ABUFU;
            uint32_t* Bn = Bs0 + ((c + 1) & 1) * ABUFU;
            #pragma unroll
            for (int i = 0; i < 4; i++) {
                uint4 va = make_uint4(rnd_tf32(ra[i].x), rnd_tf32(ra[i].y),
                                      rnd_tf32(ra[i].z), rnd_tf32(ra[i].w));
                *(uint4*)&An[(grow + i * 32) * KPAD + gcol] = va;
                uint4 vb = make_uint4(rnd_tf32(rb[i].x), rnd_tf32(rb[i].y),
                                      rnd_tf32(rb[i].z), rnd_tf32(rb[i].w));
                *(uint4*)&Bn[(grow + i * 32) * KPAD + gcol] = vb;
            }
        }
        __syncthreads();
    }

    #pragma unroll
    for (int mt = 0; mt < 4; mt++) {
        const int mrow = m0 + wm * 64 + mt * 16 + gid;
        #pragma unroll
        for (int nt = 0; nt < 4; nt++) {
            const int ncol = n0 + wn * 32 + nt * 8 + tig * 2;
            const float bx = bias[ncol];
            const float by = bias[ncol + 1];
            float v00 = acc[mt][nt][0] + bx, v01 = acc[mt][nt][1] + by;
            float v10 = acc[mt][nt][2] + bx, v11 = acc[mt][nt][3] + by;
            float2 w0, w1;
            if (outmode == 1) {
                w0 = make_float2(__uint_as_float(rnd_tf32f(v00 * oscale)),
                                 __uint_as_float(rnd_tf32f(v01 * oscale)));
                w1 = make_float2(__uint_as_float(rnd_tf32f(v10 * oscale)),
                                 __uint_as_float(rnd_tf32f(v11 * oscale)));
            } else {
                w0 = make_float2(v00, v01);
                w1 = make_float2(v10, v11);
            }
            *(float2*)(C + (long)mrow * DM + ncol) = w0;
            *(float2*)(C + (long)(mrow + 8) * DM + ncol) = w1;
        }
    }
}

// Merged QKV projection: blockIdx.z selects (input, W, bias, output, scale).
__global__ __launch_bounds__(256, 2) void qkv_gemm_kernel(
    const float* __restrict__ q, const float* __restrict__ k,
    const float* __restrict__ v,
    const float* __restrict__ Wq, const float* __restrict__ bq,
    const float* __restrict__ Wk, const float* __restrict__ bk,
    const float* __restrict__ Wv, const float* __restrict__ bv,
    float* __restrict__ oQ, float* __restrict__ oK, float* __restrict__ oV,
    float qscale)
{
    extern __shared__ uint32_t gsm[];
    const int z = blockIdx.z;
    const float* A    = (z == 0) ? q  : (z == 1) ? k  : v;
    const float* W    = (z == 0) ? Wq : (z == 1) ? Wk : Wv;
    const float* bias = (z == 0) ? bq : (z == 1) ? bk : bv;
    float*       C    = (z == 0) ? oQ : (z == 1) ? oK : oV;
    const float os    = (z == 0) ? qscale : 1.0f;
    gemm_body(A, W, bias, C, 1, os, gsm);
}

// Output projection (exact fp32 epilogue).
__global__ __launch_bounds__(256, 2) void gemm_tf32_kernel(
    const float* __restrict__ A, const float* __restrict__ W,
    const float* __restrict__ bias, float* __restrict__ C)
{
    extern __shared__ uint32_t gsm[];
    gemm_body(A, W, bias, C, 0, 1.0f, gsm);
}

// ---------------------------------------------------------------------------
// Tensor-core flash attention — R6 structure (8 warps x 16 q-rows, 256 thr,
// single-buffer K/V, two barriers/tile), with two crossbar cuts:
//  (1) V^T store XOR-swizzled: Vt[dh][key ^ 8*(dh>>4)] -> store CF (was
//      4-way); PV read uses col (8ks+tig) ^ 8*(nt>>1), still CF.
//  (2) P never touches smem: C-frag -> A-frag via quad-group shfl transpose.
// Inputs pre-rounded (Q pre-scaled) by projection GEMMs -> staging pure copy.
// Staging mapping = R6 (coalesced): krow=tid>>2, kc=(tid&3)*16.
// ---------------------------------------------------------------------------
#define APAD 68
#define ATT_SMEM_U32 (256 * APAD)        // Ps(Q) 128 rows + Ks 64 + Vt 64
#define ATT_SMEM_BYTES (ATT_SMEM_U32 * 4)

__global__ __launch_bounds__(256, 2) void attn_mma_kernel(
    const float* __restrict__ Q, const float* __restrict__ K,
    const float* __restrict__ V, float* __restrict__ Ctx)
{
    extern __shared__ uint32_t sm[];
    uint32_t* Ps = sm;                    // [128][APAD]  (Q staging only)
    uint32_t* Ks = sm + 128 * APAD;       // [64][APAD]   K[key][dh]
    uint32_t* Vt = Ks + 64 * APAD;        // [64][APAD]   V^T[dh][key-swizzled]

    const int bh = blockIdx.y;
    const int b  = bh >> 4;
    const int h  = bh & 15;
    const int q0 = blockIdx.x * 128;

    const int tid  = threadIdx.x;
    const int wid  = tid >> 5;
    const int lane = tid & 31;
    const int gid  = lane >> 2;
    const int tig  = lane & 3;
    const int r0   = wid * 16 + gid;

    const float* Qg = Q + ((long)b * SEQ) * DM + h * DH;
    const float* Kg = K + ((long)b * SEQ) * DM + h * DH;
    const float* Vg = V + ((long)b * SEQ) * DM + h * DH;

    // staging coords (R6 coalesced mapping): 4 threads/key-row, 16 dh each
    const int krow = tid >> 2;          // 0..63
    const int kc   = (tid & 3) * 16;    // 0,16,32,48
    const int vcol = krow ^ ((kc >> 4) << 3);   // swizzled V^T column

    // ---- stage Q (pre-scaled, pre-rounded): pure copy
    {
        const int row  = tid >> 1;
        const int col0 = (tid & 1) * 32;
        const uint4* qp = (const uint4*)(Qg + (long)(q0 + row) * DM + col0);
        #pragma unroll
        for (int j = 0; j < 8; j++)
            *(uint4*)&Ps[row * APAD + col0 + j * 4] = qp[j];
    }
    __syncthreads();

    // ---- persistent Q fragments
    uint32_t qf[8][4];
    #pragma unroll
    for (int ks = 0; ks < 8; ks++) {
        qf[ks][0] = Ps[r0 * APAD + ks * 8 + tig];
        qf[ks][1] = Ps[(r0 + 8) * APAD + ks * 8 + tig];
        qf[ks][2] = Ps[r0 * APAD + ks * 8 + tig + 4];
        qf[ks][3] = Ps[(r0 + 8) * APAD + ks * 8 + tig + 4];
    }

    float o[8][4];
    #pragma unroll
    for (int nt = 0; nt < 8; nt++)
        #pragma unroll
        for (int c = 0; c < 4; c++) o[nt][c] = 0.0f;
    float mr0 = -INFINITY, mr1 = -INFINITY, l0 = 0.0f, l1 = 0.0f;

    // shfl-transpose source lanes (quad-group internal)
    const int src0 = (lane & 28) | (tig >> 1);
    const int src2 = src0 + 2;

    const int NT = SEQ / 64;
    for (int it = 0; it < NT; it++) {
        __syncthreads();   // prior-tile fragment reads complete

        // ---- stage K tile [key][dh] + swizzled V^T tile (pure copy)
        {
            const long kr = (long)(it * 64 + krow);
            const uint4* kp = (const uint4*)(Kg + kr * DM + kc);
            const uint4* vp = (const uint4*)(Vg + kr * DM + kc);
            #pragma unroll
            for (int j = 0; j < 4; j++) {
                *(uint4*)&Ks[krow * APAD + kc + 4 * j] = kp[j];
                uint4 vv = vp[j];
                const int dv = kc + 4 * j;
                Vt[(dv + 0) * APAD + vcol] = vv.x;
                Vt[(dv + 1) * APAD + vcol] = vv.y;
                Vt[(dv + 2) * APAD + vcol] = vv.z;
                Vt[(dv + 3) * APAD + vcol] = vv.w;
            }
        }
        __syncthreads();

        // ---- S = Q * K^T  (per warp: 16 x 64)
        float s[8][4];
        #pragma unroll
        for (int nt = 0; nt < 8; nt++)
            #pragma unroll
            for (int c = 0; c < 4; c++) s[nt][c] = 0.0f;

        #pragma unroll
        for (int nt = 0; nt < 8; nt++) {
            const uint32_t* kb = &Ks[(nt * 8 + gid) * APAD];
            #pragma unroll
            for (int ks = 0; ks < 8; ks++) {
                uint32_t b0 = kb[ks * 8 + tig];
                uint32_t b1 = kb[ks * 8 + tig + 4];
                mma_tf32(s[nt][0], s[nt][1], s[nt][2], s[nt][3],
                         qf[ks][0], qf[ks][1], qf[ks][2], qf[ks][3], b0, b1);
            }
        }

        // ---- online softmax (log2 domain)
        float mt0 = -INFINITY, mt1 = -INFINITY;
        #pragma unroll
        for (int nt = 0; nt < 8; nt++) {
            mt0 = fmaxf(mt0, fmaxf(s[nt][0], s[nt][1]));
            mt1 = fmaxf(mt1, fmaxf(s[nt][2], s[nt][3]));
        }
        mt0 = fmaxf(mt0, __shfl_xor_sync(0xffffffffu, mt0, 1));
        mt0 = fmaxf(mt0, __shfl_xor_sync(0xffffffffu, mt0, 2));
        mt1 = fmaxf(mt1, __shfl_xor_sync(0xffffffffu, mt1, 1));
        mt1 = fmaxf(mt1, __shfl_xor_sync(0xffffffffu, mt1, 2));

        const float mn0 = fmaxf(mr0, mt0);
        const float mn1 = fmaxf(mr1, mt1);
        const float a0 = ex2f(mr0 - mn0);
        const float a1 = ex2f(mr1 - mn1);
        mr0 = mn0; mr1 = mn1;

        float rs0 = 0.0f, rs1 = 0.0f;
        #pragma unroll
        for (int nt = 0; nt < 8; nt++) {
            float p0 = ex2f(s[nt][0] - mn0);
            float p1 = ex2f(s[nt][1] - mn0);
            float p2 = ex2f(s[nt][2] - mn1);
            float p3 = ex2f(s[nt][3] - mn1);
            rs0 += p0 + p1;
            rs1 += p2 + p3;
            // keep P in registers: rounded tf32 bits replace the scores
            s[nt][0] = __uint_as_float(rnd_tf32f(p0));
            s[nt][1] = __uint_as_float(rnd_tf32f(p1));
            s[nt][2] = __uint_as_float(rnd_tf32f(p2));
            s[nt][3] = __uint_as_float(rnd_tf32f(p3));
        }
        rs0 += __shfl_xor_sync(0xffffffffu, rs0, 1);
        rs0 += __shfl_xor_sync(0xffffffffu, rs0, 2);
        rs1 += __shfl_xor_sync(0xffffffffu, rs1, 1);
        rs1 += __shfl_xor_sync(0xffffffffu, rs1, 2);

        l0 = l0 * a0 + rs0;
        l1 = l1 * a1 + rs1;
        #pragma unroll
        for (int nt = 0; nt < 8; nt++) {
            o[nt][0] *= a0; o[nt][1] *= a0;
            o[nt][2] *= a1; o[nt][3] *= a1;
        }

        // ---- O += P * V : in-register shfl transpose of P, swizzled V reads
        #pragma unroll
        for (int ks = 0; ks < 8; ks++) {
            // rows gid (c0/c1) and gid+8 (c2/c3); dest col 8ks+tig (+4)
            float t00 = __shfl_sync(0xffffffffu, s[ks][0], src0);
            float t10 = __shfl_sync(0xffffffffu, s[ks][1], src0);
            float t02 = __shfl_sync(0xffffffffu, s[ks][0], src2);
            float t12 = __shfl_sync(0xffffffffu, s[ks][1], src2);
            float u00 = __shfl_sync(0xffffffffu, s[ks][2], src0);
            float u10 = __shfl_sync(0xffffffffu, s[ks][3], src0);
            float u02 = __shfl_sync(0xffffffffu, s[ks][2], src2);
            float u12 = __shfl_sync(0xffffffffu, s[ks][3], src2);
            const bool odd = (tig & 1);
            uint32_t pa0 = __float_as_uint(odd ? t10 : t00);
            uint32_t pa1 = __float_as_uint(odd ? u10 : u00);
            uint32_t pa2 = __float_as_uint(odd ? t12 : t02);
            uint32_t pa3 = __float_as_uint(odd ? u12 : u02);

            #pragma unroll
            for (int nt = 0; nt < 8; nt++) {
                const uint32_t* vb = &Vt[(nt * 8 + gid) * APAD];
                const int ci = (ks * 8 + tig) ^ ((nt >> 1) << 3);
                uint32_t b0 = vb[ci];
                uint32_t b1 = vb[ci + 4];
                mma_tf32(o[nt][0], o[nt][1], o[nt][2], o[nt][3],
                         pa0, pa1, pa2, pa3, b0, b1);
            }
        }
    }

    // ---- epilogue: normalize and write context
    const float inv0 = 1.0f / l0;
    const float inv1 = 1.0f / l1;
    float* C0 = Ctx + ((long)b * SEQ + q0 + r0) * DM + h * DH;
    float* C1 = Ctx + ((long)b * SEQ + q0 + r0 + 8) * DM + h * DH;
    #pragma unroll
    for (int nt = 0; nt < 8; nt++) {
        const int col = nt * 8 + tig * 2;
        *(float2*)(C0 + col) = make_float2(o[nt][0] * inv0, o[nt][1] * inv0);
        *(float2*)(C1 + col) = make_float2(o[nt][2] * inv1, o[nt][3] * inv1);
    }
}

// ---------------------------------------------------------------------------
// kernel_launch  — inputs: q,k,v, Wq,bq, Wk,bk, Wv,bv, Wo,bo
// ---------------------------------------------------------------------------
extern "C" void kernel_launch(void* const* d_in, const int* in_sizes, int n_in,
                              void* d_out, int out_size)
{
    const float* q  = (const float*)d_in[0];
    const float* k  = (const float*)d_in[1];
    const float* v  = (const float*)d_in[2];
    const float* Wq = (const float*)d_in[3];
    const float* bq = (const float*)d_in[4];
    const float* Wk = (const float*)d_in[5];
    const float* bk = (const float*)d_in[6];
    const float* Wv = (const float*)d_in[7];
    const float* bv = (const float*)d_in[8];
    const float* Wo = (const float*)d_in[9];
    const float* bo = (const float*)d_in[10];
    float* out = (float*)d_out;

    float *pQ, *pK, *pV, *pC;
    cudaGetSymbolAddress((void**)&pQ, g_Q);
    cudaGetSymbolAddress((void**)&pK, g_K);
    cudaGetSymbolAddress((void**)&pV, g_V);
    cudaGetSymbolAddress((void**)&pC, g_C);

    cudaFuncSetAttribute(qkv_gemm_kernel,
                         cudaFuncAttributeMaxDynamicSharedMemorySize,
                         GEMM_SMEM_BYTES);
    cudaFuncSetAttribute(gemm_tf32_kernel,
                         cudaFuncAttributeMaxDynamicSharedMemorySize,
                         GEMM_SMEM_BYTES);
    cudaFuncSetAttribute(attn_mma_kernel,
                         cudaFuncAttributeMaxDynamicSharedMemorySize,
                         ATT_SMEM_BYTES);

    const float cf = 0.125f * 1.44269504088896f;   // 1/sqrt(64) * log2(e)

    // merged Q/K/V projections (pre-rounded tf32 outputs; Q pre-scaled)
    dim3 qkvgrid(DM / BN, MROWS / BM, 3);   // (8, 32, 3)
    qkv_gemm_kernel<<<qkvgrid, 256, GEMM_SMEM_BYTES>>>(
        q, k, v, Wq, bq, Wk, bk, Wv, bv, pQ, pK, pV, cf);

    dim3 agrid(SEQ / 128, BATCH * NH);      // (16, 32)
    attn_mma_kernel<<<agrid, 256, ATT_SMEM_BYTES>>>(pQ, pK, pV, pC);

    // final projection: exact fp32 output
    dim3 ggrid(DM / BN, MROWS / BM);        // (8, 32)
    gemm_tf32_kernel<<<ggrid, 256, GEMM_SMEM_BYTES>>>(pC, Wo, bo, out);
}

// round 15
// speedup vs baseline: 1.5781x; 1.0863x over previous
#include <cuda_runtime.h>
#include <cuda_bf16.h>
#include <math.h>
#include <cstdint>

// Problem constants
#define BATCH 2
#define SEQ 2048
#define DM 1024
#define NH 16
#define DH 64
#define MROWS (BATCH * SEQ)   // 4096

// ---------------------------------------------------------------------------
// Scratch (no cudaMalloc allowed)
// ---------------------------------------------------------------------------
__device__ __align__(256) float g_Q[MROWS * DM];
__device__ __align__(256) float g_K[MROWS * DM];
__device__ __align__(256) float g_V[MROWS * DM];
__device__ __align__(256) float g_C[MROWS * DM];

// ---------------------------------------------------------------------------
// Common helpers
// ---------------------------------------------------------------------------
__device__ __forceinline__ void mma_tf32(float& c0, float& c1, float& c2, float& c3,
                                         uint32_t a0, uint32_t a1, uint32_t a2, uint32_t a3,
                                         uint32_t b0, uint32_t b1) {
    asm volatile(
        "mma.sync.aligned.m16n8k8.row.col.f32.tf32.tf32.f32 "
        "{%0,%1,%2,%3}, {%4,%5,%6,%7}, {%8,%9}, {%0,%1,%2,%3};"
        : "+f"(c0), "+f"(c1), "+f"(c2), "+f"(c3)
        : "r"(a0), "r"(a1), "r"(a2), "r"(a3), "r"(b0), "r"(b1));
}

// fp32 -> tf32 round-to-nearest bit trick (HW truncates; +0x1000 completes RN)
__device__ __forceinline__ uint32_t rnd_tf32(uint32_t x) { return x + 0x1000u; }
__device__ __forceinline__ uint32_t rnd_tf32f(float x) { return __float_as_uint(x) + 0x1000u; }

__device__ __forceinline__ float ex2f(float x) {
    float y;
    asm("ex2.approx.f32 %0, %1;" : "=f"(y) : "f"(x));
    return y;
}

// ---------------------------------------------------------------------------
// tf32 mma.sync GEMM body: C[M,N] = A[M,K] * W[N,K]^T + bias[N]
// Tile 128x128x32, 256 threads, double-buffered smem, one barrier per chunk.
// outmode 0: write fp32 exact.
// outmode 1: write tf32-RN-rounded bits of (acc+bias)*oscale (Q/K/V — consumed
//            only by attention MMA; round-once semantics preserved).
// ---------------------------------------------------------------------------
#define BM 128
#define BN 128
#define BK 32
#define KPAD 36
#define NCHUNK (DM / BK)
#define ABUFU (BM * KPAD)
#define GEMM_SMEM_BYTES (4 * ABUFU * 4)

__device__ __forceinline__ void gemm_body(
    const float* __restrict__ A, const float* __restrict__ W,
    const float* __restrict__ bias, float* __restrict__ C,
    int outmode, float oscale, uint32_t* gsm)
{
    uint32_t* As0 = gsm;
    uint32_t* Bs0 = gsm + 2 * ABUFU;

    const int tid = threadIdx.x;
    const int wid = tid >> 5;
    const int lane = tid & 31;
    const int gid = lane >> 2;
    const int tig = lane & 3;

    const int wm = wid >> 2;
    const int wn = wid & 3;

    const int m0 = blockIdx.y * BM;
    const int n0 = blockIdx.x * BN;

    const int grow = tid >> 3;
    const int gcol = (tid & 7) * 4;

    const uint4* Ag = (const uint4*)(A + (long)(m0 + grow) * DM + gcol);
    const uint4* Wg = (const uint4*)(W + (long)(n0 + grow) * DM + gcol);

    float acc[4][4][4];
    #pragma unroll
    for (int i = 0; i < 4; i++)
        #pragma unroll
        for (int j = 0; j < 4; j++)
            #pragma unroll
            for (int c = 0; c < 4; c++) acc[i][j][c] = 0.0f;

    uint4 ra[4], rb[4];
    #pragma unroll
    for (int i = 0; i < 4; i++) {
        ra[i] = Ag[(long)i * 32 * (DM / 4)];
        rb[i] = Wg[(long)i * 32 * (DM / 4)];
    }
    #pragma unroll
    for (int i = 0; i < 4; i++) {
        uint4 va = make_uint4(rnd_tf32(ra[i].x), rnd_tf32(ra[i].y),
                              rnd_tf32(ra[i].z), rnd_tf32(ra[i].w));
        *(uint4*)&As0[(grow + i * 32) * KPAD + gcol] = va;
        uint4 vb = make_uint4(rnd_tf32(rb[i].x), rnd_tf32(rb[i].y),
                              rnd_tf32(rb[i].z), rnd_tf32(rb[i].w));
        *(uint4*)&Bs0[(grow + i * 32) * KPAD + gcol] = vb;
    }
    __syncthreads();

    for (int c = 0; c < NCHUNK; c++) {
        const uint32_t* As = As0 + (c & 1) * ABUFU;
        const uint32_t* Bs = Bs0 + (c & 1) * ABUFU;

        if (c + 1 < NCHUNK) {
            const uint4* an = Ag + (long)(c + 1) * (BK / 4);
            const uint4* bn = Wg + (long)(c + 1) * (BK / 4);
            #pragma unroll
            for (int i = 0; i < 4; i++) {
                ra[i] = an[(long)i * 32 * (DM / 4)];
                rb[i] = bn[(long)i * 32 * (DM / 4)];
            }
        }

        #pragma unroll
        for (int ks = 0; ks < 4; ks++) {
            const int k0 = ks * 8;
            uint32_t af[4][4], bf[4][2];
            #pragma unroll
            for (int mt = 0; mt < 4; mt++) {
                const int r = wm * 64 + mt * 16 + gid;
                af[mt][0] = As[r * KPAD + k0 + tig];
                af[mt][1] = As[(r + 8) * KPAD + k0 + tig];
                af[mt][2] = As[r * KPAD + k0 + tig + 4];
                af[mt][3] = As[(r + 8) * KPAD + k0 + tig + 4];
            }
            #pragma unroll
            for (int nt = 0; nt < 4; nt++) {
                const int r = wn * 32 + nt * 8 + gid;
                bf[nt][0] = Bs[r * KPAD + k0 + tig];
                bf[nt][1] = Bs[r * KPAD + k0 + tig + 4];
            }
            #pragma unroll
            for (int mt = 0; mt < 4; mt++)
                #pragma unroll
                for (int nt = 0; nt < 4; nt++)
                    mma_tf32(acc[mt][nt][0], acc[mt][nt][1],
                             acc[mt][nt][2], acc[mt][nt][3],
                             af[mt][0], af[mt][1], af[mt][2], af[mt][3],
                             bf[nt][0], bf[nt][1]);
        }

        if (c + 1 < NCHUNK) {
            uint32_t* An = As0 + ((c + 1) & 1) * ABUFU;
            uint32_t* Bn = Bs0 + ((c + 1) & 1) * ABUFU;
            #pragma unroll
            for (int i = 0; i < 4; i++) {
                uint4 va = make_uint4(rnd_tf32(ra[i].x), rnd_tf32(ra[i].y),
                                      rnd_tf32(ra[i].z), rnd_tf32(ra[i].w));
                *(uint4*)&An[(grow + i * 32) * KPAD + gcol] = va;
                uint4 vb = make_uint4(rnd_tf32(rb[i].x), rnd_tf32(rb[i].y),
                                      rnd_tf32(rb[i].z), rnd_tf32(rb[i].w));
                *(uint4*)&Bn[(grow + i * 32) * KPAD + gcol] = vb;
            }
        }
        __syncthreads();
    }

    #pragma unroll
    for (int mt = 0; mt < 4; mt++) {
        const int mrow = m0 + wm * 64 + mt * 16 + gid;
        #pragma unroll
        for (int nt = 0; nt < 4; nt++) {
            const int ncol = n0 + wn * 32 + nt * 8 + tig * 2;
            const float bx = bias[ncol];
            const float by = bias[ncol + 1];
            float v00 = acc[mt][nt][0] + bx, v01 = acc[mt][nt][1] + by;
            float v10 = acc[mt][nt][2] + bx, v11 = acc[mt][nt][3] + by;
            float2 w0, w1;
            if (outmode == 1) {
                w0 = make_float2(__uint_as_float(rnd_tf32f(v00 * oscale)),
                                 __uint_as_float(rnd_tf32f(v01 * oscale)));
                w1 = make_float2(__uint_as_float(rnd_tf32f(v10 * oscale)),
                                 __uint_as_float(rnd_tf32f(v11 * oscale)));
            } else {
                w0 = make_float2(v00, v01);
                w1 = make_float2(v10, v11);
            }
            *(float2*)(C + (long)mrow * DM + ncol) = w0;
            *(float2*)(C + (long)(mrow + 8) * DM + ncol) = w1;
        }
    }
}

// Merged QKV projection: blockIdx.z selects (input, W, bias, output, scale).
__global__ __launch_bounds__(256, 2) void qkv_gemm_kernel(
    const float* __restrict__ q, const float* __restrict__ k,
    const float* __restrict__ v,
    const float* __restrict__ Wq, const float* __restrict__ bq,
    const float* __restrict__ Wk, const float* __restrict__ bk,
    const float* __restrict__ Wv, const float* __restrict__ bv,
    float* __restrict__ oQ, float* __restrict__ oK, float* __restrict__ oV,
    float qscale)
{
    extern __shared__ uint32_t gsm[];
    const int z = blockIdx.z;
    const float* A    = (z == 0) ? q  : (z == 1) ? k  : v;
    const float* W    = (z == 0) ? Wq : (z == 1) ? Wk : Wv;
    const float* bias = (z == 0) ? bq : (z == 1) ? bk : bv;
    float*       C    = (z == 0) ? oQ : (z == 1) ? oK : oV;
    const float os    = (z == 0) ? qscale : 1.0f;
    gemm_body(A, W, bias, C, 1, os, gsm);
}

// Output projection (exact fp32 epilogue).
__global__ __launch_bounds__(256, 2) void gemm_tf32_kernel(
    const float* __restrict__ A, const float* __restrict__ W,
    const float* __restrict__ bias, float* __restrict__ C)
{
    extern __shared__ uint32_t gsm[];
    gemm_body(A, W, bias, C, 0, 1.0f, gsm);
}

// ---------------------------------------------------------------------------
// Tensor-core flash attention — R6 compute structure (8 warps x 16 q-rows,
// 256 threads, P via smem roundtrip), with:
//  (1) 128-key super-tiles: ONE barrier-pair per 128 keys (two 64-key
//      compute halves reuse the same register frame) -> barrier count halved,
//      staging LDG batch doubled (better MLP).
//  (2) V^T XOR-swizzled store: Vt[dh][key ^ 8*(dh>>4)] -> store CF (was
//      4-way); PV read col (64*half + 8ks+tig) ^ 8*(nt>>1), read CF.
// Inputs pre-rounded (Q pre-scaled) by projection GEMMs -> staging pure copy.
// Smem: Ps[128][68] (Q stage + P roundtrip), Ks[128][68], Vt[64][132]
//     = 103424 B -> 2 CTAs/SM (206.8 KB <= 228 KB).
// ---------------------------------------------------------------------------
#define APAD 68
#define VPAD 132
#define ATT_SMEM_U32 (128 * APAD + 128 * APAD + 64 * VPAD)
#define ATT_SMEM_BYTES (ATT_SMEM_U32 * 4)

__global__ __launch_bounds__(256, 2) void attn_mma_kernel(
    const float* __restrict__ Q, const float* __restrict__ K,
    const float* __restrict__ V, float* __restrict__ Ctx)
{
    extern __shared__ uint32_t sm[];
    uint32_t* Ps = sm;                    // [128][APAD]  Q stage + P roundtrip
    uint32_t* Ks = sm + 128 * APAD;       // [128][APAD]  K[key][dh]
    uint32_t* Vt = Ks + 128 * APAD;       // [64][VPAD]   V^T[dh][key-swizzled]

    const int bh = blockIdx.y;
    const int b  = bh >> 4;
    const int h  = bh & 15;
    const int q0 = blockIdx.x * 128;

    const int tid  = threadIdx.x;
    const int wid  = tid >> 5;
    const int lane = tid & 31;
    const int gid  = lane >> 2;
    const int tig  = lane & 3;
    const int r0   = wid * 16 + gid;

    const float* Qg = Q + ((long)b * SEQ) * DM + h * DH;
    const float* Kg = K + ((long)b * SEQ) * DM + h * DH;
    const float* Vg = V + ((long)b * SEQ) * DM + h * DH;

    // staging coords (R6 coalesced): 4 threads per key row, 16 dh floats each
    const int krow = tid >> 2;          // 0..63
    const int kc   = (tid & 3) * 16;    // 0,16,32,48
    const int vxor = (kc >> 4) << 3;    // 8*(dh>>4) for this thread's dh range

    // ---- stage Q (pre-scaled, pre-rounded): pure copy
    {
        const int row  = tid >> 1;
        const int col0 = (tid & 1) * 32;
        const uint4* qp = (const uint4*)(Qg + (long)(q0 + row) * DM + col0);
        #pragma unroll
        for (int j = 0; j < 8; j++)
            *(uint4*)&Ps[row * APAD + col0 + j * 4] = qp[j];
    }
    __syncthreads();

    // ---- persistent Q fragments
    uint32_t qf[8][4];
    #pragma unroll
    for (int ks = 0; ks < 8; ks++) {
        qf[ks][0] = Ps[r0 * APAD + ks * 8 + tig];
        qf[ks][1] = Ps[(r0 + 8) * APAD + ks * 8 + tig];
        qf[ks][2] = Ps[r0 * APAD + ks * 8 + tig + 4];
        qf[ks][3] = Ps[(r0 + 8) * APAD + ks * 8 + tig + 4];
    }

    float o[8][4];
    #pragma unroll
    for (int nt = 0; nt < 8; nt++)
        #pragma unroll
        for (int c = 0; c < 4; c++) o[nt][c] = 0.0f;
    float mr0 = -INFINITY, mr1 = -INFINITY, l0 = 0.0f, l1 = 0.0f;

    const int NT = SEQ / 128;   // 16 super-tiles of 128 keys
    for (int it = 0; it < NT; it++) {
        __syncthreads();   // prior super-tile fragment reads complete

        // ---- stage 128 keys: K[key][dh] + swizzled V^T[dh][key]
        #pragma unroll
        for (int half = 0; half < 2; half++) {
            const int keyl = half * 64 + krow;
            const long kr  = (long)(it * 128 + keyl);
            const uint4* kp = (const uint4*)(Kg + kr * DM + kc);
            const uint4* vp = (const uint4*)(Vg + kr * DM + kc);
            const int vcol = keyl ^ vxor;
            #pragma unroll
            for (int j = 0; j < 4; j++) {
                *(uint4*)&Ks[keyl * APAD + kc + 4 * j] = kp[j];
                uint4 vv = vp[j];
                const int dv = kc + 4 * j;
                Vt[(dv + 0) * VPAD + vcol] = vv.x;
                Vt[(dv + 1) * VPAD + vcol] = vv.y;
                Vt[(dv + 2) * VPAD + vcol] = vv.z;
                Vt[(dv + 3) * VPAD + vcol] = vv.w;
            }
        }
        __syncthreads();

        // ---- two 64-key compute halves (same register frame)
        #pragma unroll 1
        for (int half = 0; half < 2; half++) {
            const int kbase = half * 64;

            // S = Q * K^T  (per warp: 16 x 64)
            float s[8][4];
            #pragma unroll
            for (int nt = 0; nt < 8; nt++)
                #pragma unroll
                for (int c = 0; c < 4; c++) s[nt][c] = 0.0f;

            #pragma unroll
            for (int nt = 0; nt < 8; nt++) {
                const uint32_t* kb = &Ks[(kbase + nt * 8 + gid) * APAD];
                #pragma unroll
                for (int ks = 0; ks < 8; ks++) {
                    uint32_t b0 = kb[ks * 8 + tig];
                    uint32_t b1 = kb[ks * 8 + tig + 4];
                    mma_tf32(s[nt][0], s[nt][1], s[nt][2], s[nt][3],
                             qf[ks][0], qf[ks][1], qf[ks][2], qf[ks][3], b0, b1);
                }
            }

            // online softmax (log2 domain)
            float mt0 = -INFINITY, mt1 = -INFINITY;
            #pragma unroll
            for (int nt = 0; nt < 8; nt++) {
                mt0 = fmaxf(mt0, fmaxf(s[nt][0], s[nt][1]));
                mt1 = fmaxf(mt1, fmaxf(s[nt][2], s[nt][3]));
            }
            mt0 = fmaxf(mt0, __shfl_xor_sync(0xffffffffu, mt0, 1));
            mt0 = fmaxf(mt0, __shfl_xor_sync(0xffffffffu, mt0, 2));
            mt1 = fmaxf(mt1, __shfl_xor_sync(0xffffffffu, mt1, 1));
            mt1 = fmaxf(mt1, __shfl_xor_sync(0xffffffffu, mt1, 2));

            const float mn0 = fmaxf(mr0, mt0);
            const float mn1 = fmaxf(mr1, mt1);
            const float a0 = ex2f(mr0 - mn0);
            const float a1 = ex2f(mr1 - mn1);
            mr0 = mn0; mr1 = mn1;

            float rs0 = 0.0f, rs1 = 0.0f;
            #pragma unroll
            for (int nt = 0; nt < 8; nt++) {
                float p0 = ex2f(s[nt][0] - mn0);
                float p1 = ex2f(s[nt][1] - mn0);
                float p2 = ex2f(s[nt][2] - mn1);
                float p3 = ex2f(s[nt][3] - mn1);
                rs0 += p0 + p1;
                rs1 += p2 + p3;
                uint2 w0 = make_uint2(rnd_tf32f(p0), rnd_tf32f(p1));
                uint2 w1 = make_uint2(rnd_tf32f(p2), rnd_tf32f(p3));
                *(uint2*)&Ps[r0 * APAD + nt * 8 + tig * 2] = w0;
                *(uint2*)&Ps[(r0 + 8) * APAD + nt * 8 + tig * 2] = w1;
            }
            rs0 += __shfl_xor_sync(0xffffffffu, rs0, 1);
            rs0 += __shfl_xor_sync(0xffffffffu, rs0, 2);
            rs1 += __shfl_xor_sync(0xffffffffu, rs1, 1);
            rs1 += __shfl_xor_sync(0xffffffffu, rs1, 2);

            l0 = l0 * a0 + rs0;
            l1 = l1 * a1 + rs1;
            #pragma unroll
            for (int nt = 0; nt < 8; nt++) {
                o[nt][0] *= a0; o[nt][1] *= a0;
                o[nt][2] *= a1; o[nt][3] *= a1;
            }
            __syncwarp();   // P stores visible to all lanes of this warp

            // O += P * V  (swizzled V^T reads, CF)
            #pragma unroll
            for (int ks = 0; ks < 8; ks++) {
                uint32_t pa0 = Ps[r0 * APAD + ks * 8 + tig];
                uint32_t pa1 = Ps[(r0 + 8) * APAD + ks * 8 + tig];
                uint32_t pa2 = Ps[r0 * APAD + ks * 8 + tig + 4];
                uint32_t pa3 = Ps[(r0 + 8) * APAD + ks * 8 + tig + 4];
                #pragma unroll
                for (int nt = 0; nt < 8; nt++) {
                    const uint32_t* vb = &Vt[(nt * 8 + gid) * VPAD];
                    const int ci = (kbase + ks * 8 + tig) ^ ((nt >> 1) << 3);
                    uint32_t b0 = vb[ci];
                    uint32_t b1 = vb[ci + 4];
                    mma_tf32(o[nt][0], o[nt][1], o[nt][2], o[nt][3],
                             pa0, pa1, pa2, pa3, b0, b1);
                }
            }
            __syncwarp();   // PV reads of Ps done before next half overwrites
        }
    }

    // ---- epilogue: normalize and write context
    const float inv0 = 1.0f / l0;
    const float inv1 = 1.0f / l1;
    float* C0 = Ctx + ((long)b * SEQ + q0 + r0) * DM + h * DH;
    float* C1 = Ctx + ((long)b * SEQ + q0 + r0 + 8) * DM + h * DH;
    #pragma unroll
    for (int nt = 0; nt < 8; nt++) {
        const int col = nt * 8 + tig * 2;
        *(float2*)(C0 + col) = make_float2(o[nt][0] * inv0, o[nt][1] * inv0);
        *(float2*)(C1 + col) = make_float2(o[nt][2] * inv1, o[nt][3] * inv1);
    }
}

// ---------------------------------------------------------------------------
// kernel_launch  — inputs: q,k,v, Wq,bq, Wk,bk, Wv,bv, Wo,bo
// ---------------------------------------------------------------------------
extern "C" void kernel_launch(void* const* d_in, const int* in_sizes, int n_in,
                              void* d_out, int out_size)
{
    const float* q  = (const float*)d_in[0];
    const float* k  = (const float*)d_in[1];
    const float* v  = (const float*)d_in[2];
    const float* Wq = (const float*)d_in[3];
    const float* bq = (const float*)d_in[4];
    const float* Wk = (const float*)d_in[5];
    const float* bk = (const float*)d_in[6];
    const float* Wv = (const float*)d_in[7];
    const float* bv = (const float*)d_in[8];
    const float* Wo = (const float*)d_in[9];
    const float* bo = (const float*)d_in[10];
    float* out = (float*)d_out;

    float *pQ, *pK, *pV, *pC;
    cudaGetSymbolAddress((void**)&pQ, g_Q);
    cudaGetSymbolAddress((void**)&pK, g_K);
    cudaGetSymbolAddress((void**)&pV, g_V);
    cudaGetSymbolAddress((void**)&pC, g_C);

    cudaFuncSetAttribute(qkv_gemm_kernel,
                         cudaFuncAttributeMaxDynamicSharedMemorySize,
                         GEMM_SMEM_BYTES);
    cudaFuncSetAttribute(gemm_tf32_kernel,
                         cudaFuncAttributeMaxDynamicSharedMemorySize,
                         GEMM_SMEM_BYTES);
    cudaFuncSetAttribute(attn_mma_kernel,
                         cudaFuncAttributeMaxDynamicSharedMemorySize,
                         ATT_SMEM_BYTES);

    const float cf = 0.125f * 1.44269504088896f;   // 1/sqrt(64) * log2(e)

    // merged Q/K/V projections (pre-rounded tf32 outputs; Q pre-scaled)
    dim3 qkvgrid(DM / BN, MROWS / BM, 3);   // (8, 32, 3)
    qkv_gemm_kernel<<<qkvgrid, 256, GEMM_SMEM_BYTES>>>(
        q, k, v, Wq, bq, Wk, bk, Wv, bv, pQ, pK, pV, cf);

    dim3 agrid(SEQ / 128, BATCH * NH);      // (16, 32)
    attn_mma_kernel<<<agrid, 256, ATT_SMEM_BYTES>>>(pQ, pK, pV, pC);

    // final projection: exact fp32 output
    dim3 ggrid(DM / BN, MROWS / BM);        // (8, 32)
    gemm_tf32_kernel<<<ggrid, 256, GEMM_SMEM_BYTES>>>(pC, Wo, bo, out);
}

// round 16
// speedup vs baseline: 1.6120x; 1.0215x over previous
#include <cuda_runtime.h>
#include <cuda_bf16.h>
#include <math.h>
#include <cstdint>

// Problem constants
#define BATCH 2
#define SEQ 2048
#define DM 1024
#define NH 16
#define DH 64
#define MROWS (BATCH * SEQ)   // 4096

// ---------------------------------------------------------------------------
// Scratch (no cudaMalloc allowed)
// ---------------------------------------------------------------------------
__device__ __align__(256) float g_Q[MROWS * DM];
__device__ __align__(256) float g_K[MROWS * DM];
__device__ __align__(256) float g_V[MROWS * DM];
__device__ __align__(256) float g_C[MROWS * DM];

// ---------------------------------------------------------------------------
// Common helpers
// ---------------------------------------------------------------------------
__device__ __forceinline__ void mma_tf32(float& c0, float& c1, float& c2, float& c3,
                                         uint32_t a0, uint32_t a1, uint32_t a2, uint32_t a3,
                                         uint32_t b0, uint32_t b1) {
    asm volatile(
        "mma.sync.aligned.m16n8k8.row.col.f32.tf32.tf32.f32 "
        "{%0,%1,%2,%3}, {%4,%5,%6,%7}, {%8,%9}, {%0,%1,%2,%3};"
        : "+f"(c0), "+f"(c1), "+f"(c2), "+f"(c3)
        : "r"(a0), "r"(a1), "r"(a2), "r"(a3), "r"(b0), "r"(b1));
}

// fp32 -> tf32 round-to-nearest bit trick (HW truncates; +0x1000 completes RN)
__device__ __forceinline__ uint32_t rnd_tf32(uint32_t x) { return x + 0x1000u; }
__device__ __forceinline__ uint32_t rnd_tf32f(float x) { return __float_as_uint(x) + 0x1000u; }

__device__ __forceinline__ float ex2f(float x) {
    float y;
    asm("ex2.approx.f32 %0, %1;" : "=f"(y) : "f"(x));
    return y;
}

// ---------------------------------------------------------------------------
// tf32 mma.sync GEMM: C[M,N] = A[M,K] * W[N,K]^T + bias[N]
// CTA tile 128x256, 8 warps of 64x64 (mt4 x nt8) -> frag LDS/MMA = 1.0
// (was 1.5) and staging STS per output halves: crossbar-bound fix.
// 1 CTA/SM (reg frame ~233), double-buffered BK=32, one barrier per chunk.
// outmode 0: exact fp32 out. outmode 1: tf32-RN bits of (acc+bias)*oscale.
// ---------------------------------------------------------------------------
#define BM 128
#define BN 256
#define BK 32
#define KPAD 36
#define NCHUNK (DM / BK)
#define ABUF (BM * KPAD)                 // u32 per A buffer
#define BBUF (BN * KPAD)                 // u32 per B buffer
#define GEMM_SMEM_BYTES ((2 * ABUF + 2 * BBUF) * 4)   // 110592

__device__ __forceinline__ void gemm_body(
    const float* __restrict__ A, const float* __restrict__ W,
    const float* __restrict__ bias, float* __restrict__ C,
    int outmode, float oscale, uint32_t* gsm)
{
    uint32_t* As0 = gsm;                 // [2][BM*KPAD]
    uint32_t* Bs0 = gsm + 2 * ABUF;      // [2][BN*KPAD]

    const int tid = threadIdx.x;
    const int wid = tid >> 5;
    const int lane = tid & 31;
    const int gid = lane >> 2;
    const int tig = lane & 3;

    const int wm = wid >> 2;     // 0..1  (m offset wm*64)
    const int wn = wid & 3;      // 0..3  (n offset wn*64)

    const int m0 = blockIdx.y * BM;
    const int n0 = blockIdx.x * BN;

    const int grow = tid >> 3;          // 0..31
    const int gcol = (tid & 7) * 4;

    const uint4* Ag = (const uint4*)(A + (long)(m0 + grow) * DM + gcol);
    const uint4* Wg = (const uint4*)(W + (long)(n0 + grow) * DM + gcol);

    float acc[4][8][4];
    #pragma unroll
    for (int i = 0; i < 4; i++)
        #pragma unroll
        for (int j = 0; j < 8; j++)
            #pragma unroll
            for (int c = 0; c < 4; c++) acc[i][j][c] = 0.0f;

    uint4 ra[4], rb[8];
    #pragma unroll
    for (int i = 0; i < 4; i++) ra[i] = Ag[(long)i * 32 * (DM / 4)];
    #pragma unroll
    for (int i = 0; i < 8; i++) rb[i] = Wg[(long)i * 32 * (DM / 4)];

    #pragma unroll
    for (int i = 0; i < 4; i++) {
        uint4 va = make_uint4(rnd_tf32(ra[i].x), rnd_tf32(ra[i].y),
                              rnd_tf32(ra[i].z), rnd_tf32(ra[i].w));
        *(uint4*)&As0[(grow + i * 32) * KPAD + gcol] = va;
    }
    #pragma unroll
    for (int i = 0; i < 8; i++) {
        uint4 vb = make_uint4(rnd_tf32(rb[i].x), rnd_tf32(rb[i].y),
                              rnd_tf32(rb[i].z), rnd_tf32(rb[i].w));
        *(uint4*)&Bs0[(grow + i * 32) * KPAD + gcol] = vb;
    }
    __syncthreads();

    for (int c = 0; c < NCHUNK; c++) {
        const uint32_t* As = As0 + (c & 1) * ABUF;
        const uint32_t* Bs = Bs0 + (c & 1) * BBUF;

        // prefetch next chunk into registers (overlaps MMA below)
        if (c + 1 < NCHUNK) {
            const uint4* an = Ag + (long)(c + 1) * (BK / 4);
            const uint4* bn = Wg + (long)(c + 1) * (BK / 4);
            #pragma unroll
            for (int i = 0; i < 4; i++) ra[i] = an[(long)i * 32 * (DM / 4)];
            #pragma unroll
            for (int i = 0; i < 8; i++) rb[i] = bn[(long)i * 32 * (DM / 4)];
        }

        #pragma unroll
        for (int ks = 0; ks < 4; ks++) {
            const int k0 = ks * 8;
            uint32_t af[4][4], bf[8][2];
            #pragma unroll
            for (int mt = 0; mt < 4; mt++) {
                const int r = wm * 64 + mt * 16 + gid;
                af[mt][0] = As[r * KPAD + k0 + tig];
                af[mt][1] = As[(r + 8) * KPAD + k0 + tig];
                af[mt][2] = As[r * KPAD + k0 + tig + 4];
                af[mt][3] = As[(r + 8) * KPAD + k0 + tig + 4];
            }
            #pragma unroll
            for (int nt = 0; nt < 8; nt++) {
                const int r = wn * 64 + nt * 8 + gid;
                bf[nt][0] = Bs[r * KPAD + k0 + tig];
                bf[nt][1] = Bs[r * KPAD + k0 + tig + 4];
            }
            #pragma unroll
            for (int mt = 0; mt < 4; mt++)
                #pragma unroll
                for (int nt = 0; nt < 8; nt++)
                    mma_tf32(acc[mt][nt][0], acc[mt][nt][1],
                             acc[mt][nt][2], acc[mt][nt][3],
                             af[mt][0], af[mt][1], af[mt][2], af[mt][3],
                             bf[nt][0], bf[nt][1]);
        }

        // store prefetched chunk into the other buffer
        if (c + 1 < NCHUNK) {
            uint32_t* An = As0 + ((c + 1) & 1) * ABUF;
            uint32_t* Bn = Bs0 + ((c + 1) & 1) * BBUF;
            #pragma unroll
            for (int i = 0; i < 4; i++) {
                uint4 va = make_uint4(rnd_tf32(ra[i].x), rnd_tf32(ra[i].y),
                                      rnd_tf32(ra[i].z), rnd_tf32(ra[i].w));
                *(uint4*)&An[(grow + i * 32) * KPAD + gcol] = va;
            }
            #pragma unroll
            for (int i = 0; i < 8; i++) {
                uint4 vb = make_uint4(rnd_tf32(rb[i].x), rnd_tf32(rb[i].y),
                                      rnd_tf32(rb[i].z), rnd_tf32(rb[i].w));
                *(uint4*)&Bn[(grow + i * 32) * KPAD + gcol] = vb;
            }
        }
        __syncthreads();
    }

    #pragma unroll
    for (int mt = 0; mt < 4; mt++) {
        const int mrow = m0 + wm * 64 + mt * 16 + gid;
        #pragma unroll
        for (int nt = 0; nt < 8; nt++) {
            const int ncol = n0 + wn * 64 + nt * 8 + tig * 2;
            const float bx = bias[ncol];
            const float by = bias[ncol + 1];
            float v00 = acc[mt][nt][0] + bx, v01 = acc[mt][nt][1] + by;
            float v10 = acc[mt][nt][2] + bx, v11 = acc[mt][nt][3] + by;
            float2 w0, w1;
            if (outmode == 1) {
                w0 = make_float2(__uint_as_float(rnd_tf32f(v00 * oscale)),
                                 __uint_as_float(rnd_tf32f(v01 * oscale)));
                w1 = make_float2(__uint_as_float(rnd_tf32f(v10 * oscale)),
                                 __uint_as_float(rnd_tf32f(v11 * oscale)));
            } else {
                w0 = make_float2(v00, v01);
                w1 = make_float2(v10, v11);
            }
            *(float2*)(C + (long)mrow * DM + ncol) = w0;
            *(float2*)(C + (long)(mrow + 8) * DM + ncol) = w1;
        }
    }
}

// Merged QKV projection: blockIdx.z selects (input, W, bias, output, scale).
__global__ __launch_bounds__(256) void qkv_gemm_kernel(
    const float* __restrict__ q, const float* __restrict__ k,
    const float* __restrict__ v,
    const float* __restrict__ Wq, const float* __restrict__ bq,
    const float* __restrict__ Wk, const float* __restrict__ bk,
    const float* __restrict__ Wv, const float* __restrict__ bv,
    float* __restrict__ oQ, float* __restrict__ oK, float* __restrict__ oV,
    float qscale)
{
    extern __shared__ uint32_t gsm[];
    const int z = blockIdx.z;
    const float* A    = (z == 0) ? q  : (z == 1) ? k  : v;
    const float* W    = (z == 0) ? Wq : (z == 1) ? Wk : Wv;
    const float* bias = (z == 0) ? bq : (z == 1) ? bk : bv;
    float*       C    = (z == 0) ? oQ : (z == 1) ? oK : oV;
    const float os    = (z == 0) ? qscale : 1.0f;
    gemm_body(A, W, bias, C, 1, os, gsm);
}

// Output projection (exact fp32 epilogue).
__global__ __launch_bounds__(256) void gemm_tf32_kernel(
    const float* __restrict__ A, const float* __restrict__ W,
    const float* __restrict__ bias, float* __restrict__ C)
{
    extern __shared__ uint32_t gsm[];
    gemm_body(A, W, bias, C, 0, 1.0f, gsm);
}

// ---------------------------------------------------------------------------
// Tensor-core flash attention — unchanged R15 winner.
// 8 warps x 16 q-rows, 128-key super-tiles (one barrier-pair per 128 keys),
// V^T XOR-swizzled (CF store + CF read), P via smem roundtrip.
// Inputs pre-rounded (Q pre-scaled) by projection GEMMs.
// Smem: Ps[128][68] + Ks[128][68] + Vt[64][132] = 103424 B, 2 CTAs/SM.
// ---------------------------------------------------------------------------
#define APAD 68
#define VPAD 132
#define ATT_SMEM_U32 (128 * APAD + 128 * APAD + 64 * VPAD)
#define ATT_SMEM_BYTES (ATT_SMEM_U32 * 4)

__global__ __launch_bounds__(256, 2) void attn_mma_kernel(
    const float* __restrict__ Q, const float* __restrict__ K,
    const float* __restrict__ V, float* __restrict__ Ctx)
{
    extern __shared__ uint32_t sm[];
    uint32_t* Ps = sm;                    // [128][APAD]  Q stage + P roundtrip
    uint32_t* Ks = sm + 128 * APAD;       // [128][APAD]  K[key][dh]
    uint32_t* Vt = Ks + 128 * APAD;       // [64][VPAD]   V^T[dh][key-swizzled]

    const int bh = blockIdx.y;
    const int b  = bh >> 4;
    const int h  = bh & 15;
    const int q0 = blockIdx.x * 128;

    const int tid  = threadIdx.x;
    const int wid  = tid >> 5;
    const int lane = tid & 31;
    const int gid  = lane >> 2;
    const int tig  = lane & 3;
    const int r0   = wid * 16 + gid;

    const float* Qg = Q + ((long)b * SEQ) * DM + h * DH;
    const float* Kg = K + ((long)b * SEQ) * DM + h * DH;
    const float* Vg = V + ((long)b * SEQ) * DM + h * DH;

    const int krow = tid >> 2;          // 0..63
    const int kc   = (tid & 3) * 16;    // 0,16,32,48
    const int vxor = (kc >> 4) << 3;    // 8*(dh>>4)

    // ---- stage Q (pre-scaled, pre-rounded): pure copy
    {
        const int row  = tid >> 1;
        const int col0 = (tid & 1) * 32;
        const uint4* qp = (const uint4*)(Qg + (long)(q0 + row) * DM + col0);
        #pragma unroll
        for (int j = 0; j < 8; j++)
            *(uint4*)&Ps[row * APAD + col0 + j * 4] = qp[j];
    }
    __syncthreads();

    // ---- persistent Q fragments
    uint32_t qf[8][4];
    #pragma unroll
    for (int ks = 0; ks < 8; ks++) {
        qf[ks][0] = Ps[r0 * APAD + ks * 8 + tig];
        qf[ks][1] = Ps[(r0 + 8) * APAD + ks * 8 + tig];
        qf[ks][2] = Ps[r0 * APAD + ks * 8 + tig + 4];
        qf[ks][3] = Ps[(r0 + 8) * APAD + ks * 8 + tig + 4];
    }

    float o[8][4];
    #pragma unroll
    for (int nt = 0; nt < 8; nt++)
        #pragma unroll
        for (int c = 0; c < 4; c++) o[nt][c] = 0.0f;
    float mr0 = -INFINITY, mr1 = -INFINITY, l0 = 0.0f, l1 = 0.0f;

    const int NT = SEQ / 128;   // 16 super-tiles of 128 keys
    for (int it = 0; it < NT; it++) {
        __syncthreads();   // prior super-tile fragment reads complete

        // ---- stage 128 keys: K[key][dh] + swizzled V^T[dh][key]
        #pragma unroll
        for (int half = 0; half < 2; half++) {
            const int keyl = half * 64 + krow;
            const long kr  = (long)(it * 128 + keyl);
            const uint4* kp = (const uint4*)(Kg + kr * DM + kc);
            const uint4* vp = (const uint4*)(Vg + kr * DM + kc);
            const int vcol = keyl ^ vxor;
            #pragma unroll
            for (int j = 0; j < 4; j++) {
                *(uint4*)&Ks[keyl * APAD + kc + 4 * j] = kp[j];
                uint4 vv = vp[j];
                const int dv = kc + 4 * j;
                Vt[(dv + 0) * VPAD + vcol] = vv.x;
                Vt[(dv + 1) * VPAD + vcol] = vv.y;
                Vt[(dv + 2) * VPAD + vcol] = vv.z;
                Vt[(dv + 3) * VPAD + vcol] = vv.w;
            }
        }
        __syncthreads();

        // ---- two 64-key compute halves (same register frame)
        #pragma unroll 1
        for (int half = 0; half < 2; half++) {
            const int kbase = half * 64;

            float s[8][4];
            #pragma unroll
            for (int nt = 0; nt < 8; nt++)
                #pragma unroll
                for (int c = 0; c < 4; c++) s[nt][c] = 0.0f;

            #pragma unroll
            for (int nt = 0; nt < 8; nt++) {
                const uint32_t* kb = &Ks[(kbase + nt * 8 + gid) * APAD];
                #pragma unroll
                for (int ks = 0; ks < 8; ks++) {
                    uint32_t b0 = kb[ks * 8 + tig];
                    uint32_t b1 = kb[ks * 8 + tig + 4];
                    mma_tf32(s[nt][0], s[nt][1], s[nt][2], s[nt][3],
                             qf[ks][0], qf[ks][1], qf[ks][2], qf[ks][3], b0, b1);
                }
            }

            float mt0 = -INFINITY, mt1 = -INFINITY;
            #pragma unroll
            for (int nt = 0; nt < 8; nt++) {
                mt0 = fmaxf(mt0, fmaxf(s[nt][0], s[nt][1]));
                mt1 = fmaxf(mt1, fmaxf(s[nt][2], s[nt][3]));
            }
            mt0 = fmaxf(mt0, __shfl_xor_sync(0xffffffffu, mt0, 1));
            mt0 = fmaxf(mt0, __shfl_xor_sync(0xffffffffu, mt0, 2));
            mt1 = fmaxf(mt1, __shfl_xor_sync(0xffffffffu, mt1, 1));
            mt1 = fmaxf(mt1, __shfl_xor_sync(0xffffffffu, mt1, 2));

            const float mn0 = fmaxf(mr0, mt0);
            const float mn1 = fmaxf(mr1, mt1);
            const float a0 = ex2f(mr0 - mn0);
            const float a1 = ex2f(mr1 - mn1);
            mr0 = mn0; mr1 = mn1;

            float rs0 = 0.0f, rs1 = 0.0f;
            #pragma unroll
            for (int nt = 0; nt < 8; nt++) {
                float p0 = ex2f(s[nt][0] - mn0);
                float p1 = ex2f(s[nt][1] - mn0);
                float p2 = ex2f(s[nt][2] - mn1);
                float p3 = ex2f(s[nt][3] - mn1);
                rs0 += p0 + p1;
                rs1 += p2 + p3;
                uint2 w0 = make_uint2(rnd_tf32f(p0), rnd_tf32f(p1));
                uint2 w1 = make_uint2(rnd_tf32f(p2), rnd_tf32f(p3));
                *(uint2*)&Ps[r0 * APAD + nt * 8 + tig * 2] = w0;
                *(uint2*)&Ps[(r0 + 8) * APAD + nt * 8 + tig * 2] = w1;
            }
            rs0 += __shfl_xor_sync(0xffffffffu, rs0, 1);
            rs0 += __shfl_xor_sync(0xffffffffu, rs0, 2);
            rs1 += __shfl_xor_sync(0xffffffffu, rs1, 1);
            rs1 += __shfl_xor_sync(0xffffffffu, rs1, 2);

            l0 = l0 * a0 + rs0;
            l1 = l1 * a1 + rs1;
            #pragma unroll
            for (int nt = 0; nt < 8; nt++) {
                o[nt][0] *= a0; o[nt][1] *= a0;
                o[nt][2] *= a1; o[nt][3] *= a1;
            }
            __syncwarp();   // P stores visible to all lanes of this warp

            #pragma unroll
            for (int ks = 0; ks < 8; ks++) {
                uint32_t pa0 = Ps[r0 * APAD + ks * 8 + tig];
                uint32_t pa1 = Ps[(r0 + 8) * APAD + ks * 8 + tig];
                uint32_t pa2 = Ps[r0 * APAD + ks * 8 + tig + 4];
                uint32_t pa3 = Ps[(r0 + 8) * APAD + ks * 8 + tig + 4];
                #pragma unroll
                for (int nt = 0; nt < 8; nt++) {
                    const uint32_t* vb = &Vt[(nt * 8 + gid) * VPAD];
                    const int ci = (kbase + ks * 8 + tig) ^ ((nt >> 1) << 3);
                    uint32_t b0 = vb[ci];
                    uint32_t b1 = vb[ci + 4];
                    mma_tf32(o[nt][0], o[nt][1], o[nt][2], o[nt][3],
                             pa0, pa1, pa2, pa3, b0, b1);
                }
            }
            __syncwarp();   // PV reads of Ps done before next half overwrites
        }
    }

    // ---- epilogue: normalize and write context
    const float inv0 = 1.0f / l0;
    const float inv1 = 1.0f / l1;
    float* C0 = Ctx + ((long)b * SEQ + q0 + r0) * DM + h * DH;
    float* C1 = Ctx + ((long)b * SEQ + q0 + r0 + 8) * DM + h * DH;
    #pragma unroll
    for (int nt = 0; nt < 8; nt++) {
        const int col = nt * 8 + tig * 2;
        *(float2*)(C0 + col) = make_float2(o[nt][0] * inv0, o[nt][1] * inv0);
        *(float2*)(C1 + col) = make_float2(o[nt][2] * inv1, o[nt][3] * inv1);
    }
}

// ---------------------------------------------------------------------------
// kernel_launch  — inputs: q,k,v, Wq,bq, Wk,bk, Wv,bv, Wo,bo
// ---------------------------------------------------------------------------
extern "C" void kernel_launch(void* const* d_in, const int* in_sizes, int n_in,
                              void* d_out, int out_size)
{
    const float* q  = (const float*)d_in[0];
    const float* k  = (const float*)d_in[1];
    const float* v  = (const float*)d_in[2];
    const float* Wq = (const float*)d_in[3];
    const float* bq = (const float*)d_in[4];
    const float* Wk = (const float*)d_in[5];
    const float* bk = (const float*)d_in[6];
    const float* Wv = (const float*)d_in[7];
    const float* bv = (const float*)d_in[8];
    const float* Wo = (const float*)d_in[9];
    const float* bo = (const float*)d_in[10];
    float* out = (float*)d_out;

    float *pQ, *pK, *pV, *pC;
    cudaGetSymbolAddress((void**)&pQ, g_Q);
    cudaGetSymbolAddress((void**)&pK, g_K);
    cudaGetSymbolAddress((void**)&pV, g_V);
    cudaGetSymbolAddress((void**)&pC, g_C);

    cudaFuncSetAttribute(qkv_gemm_kernel,
                         cudaFuncAttributeMaxDynamicSharedMemorySize,
                         GEMM_SMEM_BYTES);
    cudaFuncSetAttribute(gemm_tf32_kernel,
                         cudaFuncAttributeMaxDynamicSharedMemorySize,
                         GEMM_SMEM_BYTES);
    cudaFuncSetAttribute(attn_mma_kernel,
                         cudaFuncAttributeMaxDynamicSharedMemorySize,
                         ATT_SMEM_BYTES);

    const float cf = 0.125f * 1.44269504088896f;   // 1/sqrt(64) * log2(e)

    // merged Q/K/V projections (pre-rounded tf32 outputs; Q pre-scaled)
    dim3 qkvgrid(DM / BN, MROWS / BM, 3);   // (4, 32, 3)
    qkv_gemm_kernel<<<qkvgrid, 256, GEMM_SMEM_BYTES>>>(
        q, k, v, Wq, bq, Wk, bk, Wv, bv, pQ, pK, pV, cf);

    dim3 agrid(SEQ / 128, BATCH * NH);      // (16, 32)
    attn_mma_kernel<<<agrid, 256, ATT_SMEM_BYTES>>>(pQ, pK, pV, pC);

    // final projection: exact fp32 output
    dim3 ggrid(DM / BN, MROWS / BM);        // (4, 32)
    gemm_tf32_kernel<<<ggrid, 256, GEMM_SMEM_BYTES>>>(pC, Wo, bo, out);
}